// round 5
// baseline (speedup 1.0000x reference)
#include <cuda_runtime.h>

#define B_  2
#define S_  2048
#define H_  1024
#define NH_ 16
#define DH_ 64
#define LOG2E 1.4426950408889634f

// Scratch Q,K,V in [B, NH, S, DH]; values pre-rounded to tf32-representable
// fp32 (Q additionally pre-scaled by log2e/sqrt(DH)).
__device__ float g_q[(size_t)B_ * NH_ * S_ * DH_];
__device__ float g_k[(size_t)B_ * NH_ * S_ * DH_];
__device__ float g_v[(size_t)B_ * NH_ * S_ * DH_];

__device__ __forceinline__ unsigned f2tf32(float x) {
    unsigned u;
    asm("cvt.rna.tf32.f32 %0, %1;" : "=r"(u) : "f"(x));
    return u;
}
__device__ __forceinline__ float ex2(float x) {
    float y;
    asm("ex2.approx.ftz.f32 %0, %1;" : "=f"(y) : "f"(x));
    return y;
}
__device__ __forceinline__ void cpa16(unsigned dst, const void* src) {
    asm volatile("cp.async.cg.shared.global [%0], [%1], 16;" :: "r"(dst), "l"(src));
}

// D += A * B  (m16n8k8, tf32 inputs, fp32 accumulate, A row-major, B col-major)
__device__ __forceinline__ void mma8(float* d, const unsigned* a, const unsigned* b) {
    asm volatile(
        "mma.sync.aligned.m16n8k8.row.col.f32.tf32.tf32.f32 "
        "{%0,%1,%2,%3}, {%4,%5,%6,%7}, {%8,%9}, {%0,%1,%2,%3};"
        : "+f"(d[0]), "+f"(d[1]), "+f"(d[2]), "+f"(d[3])
        : "r"(a[0]), "r"(a[1]), "r"(a[2]), "r"(a[3]), "r"(b[0]), "r"(b[1]));
}

// ---------------------------------------------------------------------------
// Kernel 1: QKV projection, TF32 GEMM, double-buffered smem + reg prefetch.
// Epilogue rounds outputs to tf32-representable fp32 so flash_attn can copy
// bits raw (cp.async) with zero conversion error.
// ---------------------------------------------------------------------------
#define AST 36
#define BST 136

__global__ __launch_bounds__(256, 2) void qkv_gemm(
    const float* __restrict__ hs,
    const float* __restrict__ Wq, const float* __restrict__ bq,
    const float* __restrict__ Wk, const float* __restrict__ bk,
    const float* __restrict__ Wv, const float* __restrict__ bv)
{
    extern __shared__ unsigned gsm[];
    unsigned* Asb[2] = { gsm, gsm + 128 * AST };
    unsigned* Bsb[2] = { gsm + 2 * 128 * AST, gsm + 2 * 128 * AST + 32 * BST };

    const int z = blockIdx.z;
    const float* W    = (z == 0) ? Wq : (z == 1) ? Wk : Wv;
    const float* bias = (z == 0) ? bq : (z == 1) ? bk : bv;
    float* outp       = (z == 0) ? g_q : (z == 1) ? g_k : g_v;
    const float oscale = (z == 0) ? 0.125f * LOG2E : 1.0f;

    const int tid  = threadIdx.x;
    const int lane = tid & 31;
    const int wid  = tid >> 5;
    const int g = lane >> 2, j = lane & 3;
    const int wm = wid >> 2, wn = wid & 3;

    const int m0 = blockIdx.y * 128;
    const int n0 = blockIdx.x * 128;

    float acc[4][4][4];
    #pragma unroll
    for (int mt = 0; mt < 4; mt++)
        #pragma unroll
        for (int nt = 0; nt < 4; nt++)
            #pragma unroll
            for (int r = 0; r < 4; r++) acc[mt][nt][r] = 0.f;

    const int am  = tid >> 3, ak  = (tid & 7) * 4;
    const int ldk = tid >> 5, ldn = (tid & 31) * 4;

    float4 pa[4], pb[4];
    #pragma unroll
    for (int p = 0; p < 4; p++) {
        pa[p] = *reinterpret_cast<const float4*>(hs + (size_t)(m0 + am + p * 32) * H_ + ak);
        pb[p] = *reinterpret_cast<const float4*>(W + (size_t)(ldk + p * 8) * H_ + n0 + ldn);
    }
    #pragma unroll
    for (int p = 0; p < 4; p++) {
        uint4 ua = { f2tf32(pa[p].x), f2tf32(pa[p].y), f2tf32(pa[p].z), f2tf32(pa[p].w) };
        *reinterpret_cast<uint4*>(&Asb[0][(am + p * 32) * AST + ak]) = ua;
        uint4 ub = { f2tf32(pb[p].x), f2tf32(pb[p].y), f2tf32(pb[p].z), f2tf32(pb[p].w) };
        *reinterpret_cast<uint4*>(&Bsb[0][(ldk + p * 8) * BST + ldn]) = ub;
    }
    __syncthreads();

    #pragma unroll 2
    for (int kc = 0; kc < H_ / 32; kc++) {
        const int cur = kc & 1;
        if (kc < H_ / 32 - 1) {
            const int k0 = (kc + 1) * 32;
            #pragma unroll
            for (int p = 0; p < 4; p++) {
                pa[p] = *reinterpret_cast<const float4*>(
                    hs + (size_t)(m0 + am + p * 32) * H_ + k0 + ak);
                pb[p] = *reinterpret_cast<const float4*>(
                    W + (size_t)(k0 + ldk + p * 8) * H_ + n0 + ldn);
            }
        }

        const unsigned* As = Asb[cur];
        const unsigned* Bs = Bsb[cur];
        #pragma unroll
        for (int kd = 0; kd < 4; kd++) {
            unsigned af[4][4];
            #pragma unroll
            for (int mt = 0; mt < 4; mt++) {
                const int row = wm * 64 + mt * 16 + g;
                const int col = kd * 8 + j;
                af[mt][0] = As[row * AST + col];
                af[mt][1] = As[(row + 8) * AST + col];
                af[mt][2] = As[row * AST + col + 4];
                af[mt][3] = As[(row + 8) * AST + col + 4];
            }
            #pragma unroll
            for (int nt = 0; nt < 4; nt++) {
                unsigned bf[2];
                const int col = wn * 32 + nt * 8 + g;
                bf[0] = Bs[(kd * 8 + j) * BST + col];
                bf[1] = Bs[(kd * 8 + j + 4) * BST + col];
                #pragma unroll
                for (int mt = 0; mt < 4; mt++)
                    mma8(acc[mt][nt], af[mt], bf);
            }
        }

        if (kc < H_ / 32 - 1) {
            const int nxt = cur ^ 1;
            #pragma unroll
            for (int p = 0; p < 4; p++) {
                uint4 ua = { f2tf32(pa[p].x), f2tf32(pa[p].y), f2tf32(pa[p].z), f2tf32(pa[p].w) };
                *reinterpret_cast<uint4*>(&Asb[nxt][(am + p * 32) * AST + ak]) = ua;
                uint4 ub = { f2tf32(pb[p].x), f2tf32(pb[p].y), f2tf32(pb[p].z), f2tf32(pb[p].w) };
                *reinterpret_cast<uint4*>(&Bsb[nxt][(ldk + p * 8) * BST + ldn]) = ub;
            }
        }
        __syncthreads();
    }

    // Epilogue: bias + scale, round to tf32-representable, scatter.
    #pragma unroll
    for (int mt = 0; mt < 4; mt++) {
        #pragma unroll
        for (int nt = 0; nt < 4; nt++) {
            const int c = n0 + wn * 32 + nt * 8 + 2 * j;
            const int h = c >> 6, d = c & 63;
            const float b0 = bias[c], b1 = bias[c + 1];
            #pragma unroll
            for (int half = 0; half < 2; half++) {
                const int m = m0 + wm * 64 + mt * 16 + g + half * 8;
                const int bb = m >> 11;
                const int s = m & (S_ - 1);
                float2 o;
                o.x = __uint_as_float(f2tf32((acc[mt][nt][half * 2 + 0] + b0) * oscale));
                o.y = __uint_as_float(f2tf32((acc[mt][nt][half * 2 + 1] + b1) * oscale));
                *reinterpret_cast<float2*>(
                    outp + (((size_t)bb * NH_ + h) * S_ + s) * DH_ + d) = o;
            }
        }
    }
}

// ---------------------------------------------------------------------------
// Kernel 2: TF32 flash attention. grid = (S/128, NH, B), 256 threads,
// 2 CTAs/SM. cp.async double-buffered K/V in natural [kv][d] layout
// (K stride 68, V stride 72: both conflict-free for B-fragment reads).
// P never touches smem: quad shuffles remap mma-C layout -> mma-A layout.
// Softmax in base-2 domain (Q pre-scaled by log2e/8 in projection).
// ---------------------------------------------------------------------------
#define KST2 68   // K rows [kv][d]
#define VST  72   // V rows [kv][d]
#define QST  68   // Q rows [q][d]

__global__ __launch_bounds__(256, 2) void flash_attn(
    const float* __restrict__ mask, float* __restrict__ out)
{
    extern __shared__ unsigned smem[];
    unsigned* Ksb[2] = { smem, smem + 64 * KST2 };
    unsigned* Vsb[2] = { smem + 2 * 64 * KST2, smem + 2 * 64 * KST2 + 64 * VST };
    unsigned* Qs     = smem + 2 * 64 * KST2 + 2 * 64 * VST;

    const int tid  = threadIdx.x;
    const int lane = tid & 31;
    const int wid  = tid >> 5;
    const int g = lane >> 2, j = lane & 3;

    const int qbase = blockIdx.x * 128;
    const int h = blockIdx.y, bb = blockIdx.z;
    const size_t base = ((size_t)bb * NH_ + h) * S_ * DH_;
    const float* Qg = g_q + base;
    const float* Kg = g_k + base;
    const float* Vg = g_v + base;
    const float* mrow = mask + (size_t)bb * S_;

    const unsigned qs_base = (unsigned)__cvta_generic_to_shared(Qs);
    const unsigned ks_base[2] = {
        (unsigned)__cvta_generic_to_shared(Ksb[0]),
        (unsigned)__cvta_generic_to_shared(Ksb[1]) };
    const unsigned vs_base[2] = {
        (unsigned)__cvta_generic_to_shared(Vsb[0]),
        (unsigned)__cvta_generic_to_shared(Vsb[1]) };

    // Prologue group 0: Q tile + K0 + V0 (raw 16B copies; data pre-rounded).
    #pragma unroll
    for (int t = 0; t < 8; t++) {
        const int f = t * 256 + tid;
        const int r = f >> 4, c = f & 15;
        cpa16(qs_base + (r * QST) * 4 + c * 16, Qg + (size_t)(qbase + r) * DH_ + c * 4);
    }
    #pragma unroll
    for (int t = 0; t < 4; t++) {
        const int f = t * 256 + tid;
        const int r = f >> 4, c = f & 15;
        cpa16(ks_base[0] + (r * KST2) * 4 + c * 16, Kg + (size_t)r * DH_ + c * 4);
        cpa16(vs_base[0] + (r * VST) * 4 + c * 16, Vg + (size_t)r * DH_ + c * 4);
    }
    asm volatile("cp.async.commit_group;");

    float m0 = -1e30f, m1 = -1e30f, l0 = 0.f, l1 = 0.f;
    float O[8][4];
    #pragma unroll
    for (int nt = 0; nt < 8; nt++)
        #pragma unroll
        for (int r = 0; r < 4; r++) O[nt][r] = 0.f;

    const int prow = wid * 16 + g;
    const unsigned* qrow = &Qs[prow * QST];
    const int srcA = (lane & 28) | (j >> 1);   // quad lane holding col j
    const int srcB = srcA + 2;                 // quad lane holding col j+4

    for (int kc = 0; kc < S_ / 64; kc++) {
        const int cur = kc & 1;
        if (kc < S_ / 64 - 1) {
            const int nxt = cur ^ 1;
            #pragma unroll
            for (int t = 0; t < 4; t++) {
                const int f = t * 256 + tid;
                const int r = f >> 4, c = f & 15;
                cpa16(ks_base[nxt] + (r * KST2) * 4 + c * 16,
                      Kg + (size_t)((kc + 1) * 64 + r) * DH_ + c * 4);
                cpa16(vs_base[nxt] + (r * VST) * 4 + c * 16,
                      Vg + (size_t)((kc + 1) * 64 + r) * DH_ + c * 4);
            }
            asm volatile("cp.async.commit_group;");
            asm volatile("cp.async.wait_group 1;");
        } else {
            asm volatile("cp.async.wait_group 0;");
        }
        __syncthreads();

        const unsigned* Ks = Ksb[cur];
        const unsigned* Vs = Vsb[cur];

        // S = Q @ K^T  (16 x 64 per warp), base-2 scaled.
        float Sa[8][4];
        #pragma unroll
        for (int nt = 0; nt < 8; nt++)
            #pragma unroll
            for (int r = 0; r < 4; r++) Sa[nt][r] = 0.f;

        #pragma unroll
        for (int kd = 0; kd < 8; kd++) {
            unsigned Qf[4];
            const int col = kd * 8 + j;
            Qf[0] = qrow[col];
            Qf[1] = qrow[8 * QST + col];
            Qf[2] = qrow[col + 4];
            Qf[3] = qrow[8 * QST + col + 4];
            #pragma unroll
            for (int nt = 0; nt < 8; nt++) {
                unsigned bf[2];
                bf[0] = Ks[(nt * 8 + g) * KST2 + col];
                bf[1] = Ks[(nt * 8 + g) * KST2 + col + 4];
                mma8(Sa[nt], Qf, bf);
            }
        }

        // Mask (scaled to base-2) + tile max
        float tm0 = -1e30f, tm1 = -1e30f;
        #pragma unroll
        for (int nt = 0; nt < 8; nt++) {
            const float2 mk = __ldg(reinterpret_cast<const float2*>(
                mrow + kc * 64 + nt * 8 + 2 * j));
            const float mk0 = mk.x * LOG2E, mk1 = mk.y * LOG2E;
            Sa[nt][0] += mk0; Sa[nt][1] += mk1;
            Sa[nt][2] += mk0; Sa[nt][3] += mk1;
            tm0 = fmaxf(tm0, fmaxf(Sa[nt][0], Sa[nt][1]));
            tm1 = fmaxf(tm1, fmaxf(Sa[nt][2], Sa[nt][3]));
        }
        tm0 = fmaxf(tm0, __shfl_xor_sync(0xffffffffu, tm0, 1));
        tm0 = fmaxf(tm0, __shfl_xor_sync(0xffffffffu, tm0, 2));
        tm1 = fmaxf(tm1, __shfl_xor_sync(0xffffffffu, tm1, 1));
        tm1 = fmaxf(tm1, __shfl_xor_sync(0xffffffffu, tm1, 2));

        const float nm0 = fmaxf(m0, tm0), nm1 = fmaxf(m1, tm1);
        const float al0 = ex2(m0 - nm0), al1 = ex2(m1 - nm1);
        m0 = nm0; m1 = nm1;

        // P = 2^(S - m) in place, row sums.
        float rs0 = 0.f, rs1 = 0.f;
        #pragma unroll
        for (int nt = 0; nt < 8; nt++) {
            Sa[nt][0] = ex2(Sa[nt][0] - nm0);
            Sa[nt][1] = ex2(Sa[nt][1] - nm0);
            Sa[nt][2] = ex2(Sa[nt][2] - nm1);
            Sa[nt][3] = ex2(Sa[nt][3] - nm1);
            rs0 += Sa[nt][0] + Sa[nt][1];
            rs1 += Sa[nt][2] + Sa[nt][3];
        }
        rs0 += __shfl_xor_sync(0xffffffffu, rs0, 1);
        rs0 += __shfl_xor_sync(0xffffffffu, rs0, 2);
        rs1 += __shfl_xor_sync(0xffffffffu, rs1, 1);
        rs1 += __shfl_xor_sync(0xffffffffu, rs1, 2);
        l0 = l0 * al0 + rs0;
        l1 = l1 * al1 + rs1;

        #pragma unroll
        for (int nt = 0; nt < 8; nt++) {
            O[nt][0] *= al0; O[nt][1] *= al0;
            O[nt][2] *= al1; O[nt][3] *= al1;
        }

        // O += P @ V. P fragments built by quad shuffles (C-layout -> A-layout).
        #pragma unroll
        for (int kk = 0; kk < 8; kk++) {
            const float v0 = Sa[kk][0], v1 = Sa[kk][1];
            const float v2 = Sa[kk][2], v3 = Sa[kk][3];
            const float a0 = __shfl_sync(0xffffffffu, v0, srcA);
            const float a1 = __shfl_sync(0xffffffffu, v1, srcA);
            const float b0_ = __shfl_sync(0xffffffffu, v2, srcA);
            const float b1_ = __shfl_sync(0xffffffffu, v3, srcA);
            const float c0 = __shfl_sync(0xffffffffu, v0, srcB);
            const float c1 = __shfl_sync(0xffffffffu, v1, srcB);
            const float d0 = __shfl_sync(0xffffffffu, v2, srcB);
            const float d1 = __shfl_sync(0xffffffffu, v3, srcB);
            unsigned Pf[4];
            Pf[0] = f2tf32((j & 1) ? a1 : a0);   // P[g][kk*8+j]
            Pf[1] = f2tf32((j & 1) ? b1_ : b0_); // P[g+8][kk*8+j]
            Pf[2] = f2tf32((j & 1) ? c1 : c0);   // P[g][kk*8+j+4]
            Pf[3] = f2tf32((j & 1) ? d1 : d0);   // P[g+8][kk*8+j+4]
            #pragma unroll
            for (int nt = 0; nt < 8; nt++) {
                unsigned bf[2];
                bf[0] = Vs[(kk * 8 + j) * VST + nt * 8 + g];
                bf[1] = Vs[(kk * 8 + j + 4) * VST + nt * 8 + g];
                mma8(O[nt], Pf, bf);
            }
        }
        __syncthreads();   // all reads of buf[cur] done before kc+1 overwrites it
    }

    // Epilogue: normalize, write merged-head [B,S,H] output.
    const float inv0 = 1.f / l0, inv1 = 1.f / l1;
    const int r0 = qbase + prow;
    #pragma unroll
    for (int nt = 0; nt < 8; nt++) {
        const int c = h * 64 + nt * 8 + 2 * j;
        float2 o0, o1;
        o0.x = O[nt][0] * inv0; o0.y = O[nt][1] * inv0;
        o1.x = O[nt][2] * inv1; o1.y = O[nt][3] * inv1;
        *reinterpret_cast<float2*>(out + ((size_t)bb * S_ + r0) * H_ + c) = o0;
        *reinterpret_cast<float2*>(out + ((size_t)bb * S_ + r0 + 8) * H_ + c) = o1;
    }
}

extern "C" void kernel_launch(void* const* d_in, const int* in_sizes, int n_in,
                              void* d_out, int out_size)
{
    const float* hs   = (const float*)d_in[0];
    const float* mask = (const float*)d_in[1];
    const float* Wq   = (const float*)d_in[2];
    const float* bq   = (const float*)d_in[3];
    const float* Wk   = (const float*)d_in[4];
    const float* bk   = (const float*)d_in[5];
    const float* Wv   = (const float*)d_in[6];
    const float* bv   = (const float*)d_in[7];
    float* out = (float*)d_out;

    const int smem_gemm = (2 * 128 * AST + 2 * 32 * BST) * 4;
    cudaFuncSetAttribute(qkv_gemm, cudaFuncAttributeMaxDynamicSharedMemorySize, smem_gemm);
    dim3 g1(H_ / 128, (B_ * S_) / 128, 3);
    qkv_gemm<<<g1, 256, smem_gemm>>>(hs, Wq, bq, Wk, bk, Wv, bv);

    const int smem_att = (2 * 64 * KST2 + 2 * 64 * VST + 128 * QST) * 4;  // 106496 B
    cudaFuncSetAttribute(flash_attn, cudaFuncAttributeMaxDynamicSharedMemorySize, smem_att);
    dim3 g2(S_ / 128, NH_, B_);
    flash_attn<<<g2, 256, smem_att>>>(mask, out);
}

// round 7
// speedup vs baseline: 1.4310x; 1.4310x over previous
#include <cuda_runtime.h>
#include <cuda_fp16.h>
#include <cstdint>

#define B_  2
#define S_  2048
#define H_  1024
#define NH_ 16
#define DH_ 64
#define LOG2E 1.4426950408889634f

// Scratch (fp16): Q,K in [B,NH,S,DH]; V stored TRANSPOSED per head [B,NH,DH,S].
// Q pre-scaled by log2e/sqrt(DH).
__device__ __half g_q[(size_t)B_ * NH_ * S_ * DH_];
__device__ __half g_k[(size_t)B_ * NH_ * S_ * DH_];
__device__ __half g_v[(size_t)B_ * NH_ * S_ * DH_];

__device__ __forceinline__ unsigned f2tf32(float x) {
    unsigned u;
    asm("cvt.rna.tf32.f32 %0, %1;" : "=r"(u) : "f"(x));
    return u;
}
__device__ __forceinline__ float ex2(float x) {
    float y;
    asm("ex2.approx.ftz.f32 %0, %1;" : "=f"(y) : "f"(x));
    return y;
}
__device__ __forceinline__ unsigned packh2(float lo, float hi) {
    unsigned r;
    asm("cvt.rn.f16x2.f32 %0, %1, %2;" : "=r"(r) : "f"(hi), "f"(lo));
    return r;
}
__device__ __forceinline__ void cpa16(unsigned dst, const void* src) {
    asm volatile("cp.async.cg.shared.global [%0], [%1], 16;" :: "r"(dst), "l"(src));
}
// tf32 m16n8k8 (QKV projection)
__device__ __forceinline__ void mma8(float* d, const unsigned* a, const unsigned* b) {
    asm volatile(
        "mma.sync.aligned.m16n8k8.row.col.f32.tf32.tf32.f32 "
        "{%0,%1,%2,%3}, {%4,%5,%6,%7}, {%8,%9}, {%0,%1,%2,%3};"
        : "+f"(d[0]), "+f"(d[1]), "+f"(d[2]), "+f"(d[3])
        : "r"(a[0]), "r"(a[1]), "r"(a[2]), "r"(a[3]), "r"(b[0]), "r"(b[1]));
}
// fp16 m16n8k16, fp32 accumulate (flash attention)
__device__ __forceinline__ void mma16(float* d, const unsigned* a, const unsigned* b) {
    asm volatile(
        "mma.sync.aligned.m16n8k16.row.col.f32.f16.f16.f32 "
        "{%0,%1,%2,%3}, {%4,%5,%6,%7}, {%8,%9}, {%0,%1,%2,%3};"
        : "+f"(d[0]), "+f"(d[1]), "+f"(d[2]), "+f"(d[3])
        : "r"(a[0]), "r"(a[1]), "r"(a[2]), "r"(a[3]), "r"(b[0]), "r"(b[1]));
}

// ---------------------------------------------------------------------------
// Kernel 1: QKV projection, TF32 GEMM (proven R5 core). Epilogue converts to
// fp16; V scattered transposed [b,h,d,s]; Q scaled by log2e/8.
// ---------------------------------------------------------------------------
#define AST 36
#define BST 136

__global__ __launch_bounds__(256, 2) void qkv_gemm(
    const float* __restrict__ hs,
    const float* __restrict__ Wq, const float* __restrict__ bq,
    const float* __restrict__ Wk, const float* __restrict__ bk,
    const float* __restrict__ Wv, const float* __restrict__ bv)
{
    extern __shared__ unsigned gsm[];
    unsigned* Asb[2] = { gsm, gsm + 128 * AST };
    unsigned* Bsb[2] = { gsm + 2 * 128 * AST, gsm + 2 * 128 * AST + 32 * BST };

    const int z = blockIdx.z;
    const float* W    = (z == 0) ? Wq : (z == 1) ? Wk : Wv;
    const float* bias = (z == 0) ? bq : (z == 1) ? bk : bv;
    __half* outp      = (z == 0) ? g_q : (z == 1) ? g_k : g_v;
    const float oscale = (z == 0) ? 0.125f * LOG2E : 1.0f;

    const int tid  = threadIdx.x;
    const int lane = tid & 31;
    const int wid  = tid >> 5;
    const int g = lane >> 2, j = lane & 3;
    const int wm = wid >> 2, wn = wid & 3;

    const int m0 = blockIdx.y * 128;
    const int n0 = blockIdx.x * 128;

    float acc[4][4][4];
    #pragma unroll
    for (int mt = 0; mt < 4; mt++)
        #pragma unroll
        for (int nt = 0; nt < 4; nt++)
            #pragma unroll
            for (int r = 0; r < 4; r++) acc[mt][nt][r] = 0.f;

    const int am  = tid >> 3, ak  = (tid & 7) * 4;
    const int ldk = tid >> 5, ldn = (tid & 31) * 4;

    float4 pa[4], pb[4];
    #pragma unroll
    for (int p = 0; p < 4; p++) {
        pa[p] = *reinterpret_cast<const float4*>(hs + (size_t)(m0 + am + p * 32) * H_ + ak);
        pb[p] = *reinterpret_cast<const float4*>(W + (size_t)(ldk + p * 8) * H_ + n0 + ldn);
    }
    #pragma unroll
    for (int p = 0; p < 4; p++) {
        uint4 ua = { f2tf32(pa[p].x), f2tf32(pa[p].y), f2tf32(pa[p].z), f2tf32(pa[p].w) };
        *reinterpret_cast<uint4*>(&Asb[0][(am + p * 32) * AST + ak]) = ua;
        uint4 ub = { f2tf32(pb[p].x), f2tf32(pb[p].y), f2tf32(pb[p].z), f2tf32(pb[p].w) };
        *reinterpret_cast<uint4*>(&Bsb[0][(ldk + p * 8) * BST + ldn]) = ub;
    }
    __syncthreads();

    #pragma unroll 2
    for (int kc = 0; kc < H_ / 32; kc++) {
        const int cur = kc & 1;
        if (kc < H_ / 32 - 1) {
            const int k0 = (kc + 1) * 32;
            #pragma unroll
            for (int p = 0; p < 4; p++) {
                pa[p] = *reinterpret_cast<const float4*>(
                    hs + (size_t)(m0 + am + p * 32) * H_ + k0 + ak);
                pb[p] = *reinterpret_cast<const float4*>(
                    W + (size_t)(k0 + ldk + p * 8) * H_ + n0 + ldn);
            }
        }
        const unsigned* As = Asb[cur];
        const unsigned* Bs = Bsb[cur];
        #pragma unroll
        for (int kd = 0; kd < 4; kd++) {
            unsigned af[4][4];
            #pragma unroll
            for (int mt = 0; mt < 4; mt++) {
                const int row = wm * 64 + mt * 16 + g;
                const int col = kd * 8 + j;
                af[mt][0] = As[row * AST + col];
                af[mt][1] = As[(row + 8) * AST + col];
                af[mt][2] = As[row * AST + col + 4];
                af[mt][3] = As[(row + 8) * AST + col + 4];
            }
            #pragma unroll
            for (int nt = 0; nt < 4; nt++) {
                unsigned bf[2];
                const int col = wn * 32 + nt * 8 + g;
                bf[0] = Bs[(kd * 8 + j) * BST + col];
                bf[1] = Bs[(kd * 8 + j + 4) * BST + col];
                #pragma unroll
                for (int mt = 0; mt < 4; mt++)
                    mma8(acc[mt][nt], af[mt], bf);
            }
        }
        if (kc < H_ / 32 - 1) {
            const int nxt = cur ^ 1;
            #pragma unroll
            for (int p = 0; p < 4; p++) {
                uint4 ua = { f2tf32(pa[p].x), f2tf32(pa[p].y), f2tf32(pa[p].z), f2tf32(pa[p].w) };
                *reinterpret_cast<uint4*>(&Asb[nxt][(am + p * 32) * AST + ak]) = ua;
                uint4 ub = { f2tf32(pb[p].x), f2tf32(pb[p].y), f2tf32(pb[p].z), f2tf32(pb[p].w) };
                *reinterpret_cast<uint4*>(&Bsb[nxt][(ldk + p * 8) * BST + ldn]) = ub;
            }
        }
        __syncthreads();
    }

    #pragma unroll
    for (int mt = 0; mt < 4; mt++) {
        #pragma unroll
        for (int nt = 0; nt < 4; nt++) {
            const int c = n0 + wn * 32 + nt * 8 + 2 * j;
            const int h = c >> 6, d = c & 63;
            const float b0 = bias[c], b1 = bias[c + 1];
            #pragma unroll
            for (int half = 0; half < 2; half++) {
                const int m = m0 + wm * 64 + mt * 16 + g + half * 8;
                const int bb = m >> 11;
                const int s = m & (S_ - 1);
                const float v0 = (acc[mt][nt][half * 2 + 0] + b0) * oscale;
                const float v1 = (acc[mt][nt][half * 2 + 1] + b1) * oscale;
                if (z == 2) {   // V: transposed scatter [b,h,d,s]
                    const size_t hb = ((size_t)bb * NH_ + h) * DH_;
                    outp[(hb + d) * S_ + s]     = __float2half_rn(v0);
                    outp[(hb + d + 1) * S_ + s] = __float2half_rn(v1);
                } else {
                    __half2 o = __floats2half2_rn(v0, v1);
                    *reinterpret_cast<__half2*>(
                        outp + (((size_t)bb * NH_ + h) * S_ + s) * DH_ + d) = o;
                }
            }
        }
    }
}

// ---------------------------------------------------------------------------
// Kernel 2: fp16 flash attention (m16n8k16). grid = (S/128, NH, B),
// 256 threads, 2 CTAs/SM. K [kv][d], V^T [d][kv], Q [q][d] in smem, stride
// 72 halves (conflict-free for all fragment patterns). P stays in registers:
// C-fragments pack directly into A-fragments via cvt.rn.f16x2 (no shuffles).
// cp.async double-buffered K/V. Softmax in base-2 domain.
// ---------------------------------------------------------------------------
#define FST 72            // halves per smem row (144 B)
#define FQ_OFF 0          // halves
#define FK_OFF(b) (9216 + (b) * 4608)
#define FV_OFF(b) (18432 + (b) * 4608)
#define F_TOTAL_BYTES 55296

__global__ __launch_bounds__(256, 2) void flash_attn_h(
    const float* __restrict__ mask, float* __restrict__ out)
{
    extern __shared__ __half smh[];
    const uint32_t sb = (uint32_t)__cvta_generic_to_shared(smh);
    const unsigned* Qw = reinterpret_cast<const unsigned*>(smh + FQ_OFF);

    const int tid  = threadIdx.x;
    const int lane = tid & 31;
    const int wid  = tid >> 5;
    const int g = lane >> 2, j = lane & 3;

    const int qbase = blockIdx.x * 128;
    const int h = blockIdx.y, bb = blockIdx.z;
    const __half* Qg = g_q + ((size_t)bb * NH_ + h) * S_ * DH_;
    const __half* Kg = g_k + ((size_t)bb * NH_ + h) * S_ * DH_;
    const __half* Vt = g_v + ((size_t)bb * NH_ + h) * DH_ * S_;
    const float* mrow = mask + (size_t)bb * S_;

    // Prologue: Q (128 rows x 8 chunks) + K0/V0 (64 rows x 8 chunks each)
    #pragma unroll
    for (int t = 0; t < 4; t++) {
        const int f = t * 256 + tid;
        const int r = f >> 3, c = f & 7;
        cpa16(sb + FQ_OFF * 2 + r * 144 + c * 16, Qg + (size_t)(qbase + r) * DH_ + c * 8);
    }
    #pragma unroll
    for (int t = 0; t < 2; t++) {
        const int f = t * 256 + tid;
        const int r = f >> 3, c = f & 7;
        cpa16(sb + FK_OFF(0) * 2 + r * 144 + c * 16, Kg + (size_t)r * DH_ + c * 8);
        cpa16(sb + FV_OFF(0) * 2 + r * 144 + c * 16, Vt + (size_t)r * S_ + c * 8);
    }
    asm volatile("cp.async.commit_group;");

    float m0 = -1e30f, m1 = -1e30f, l0 = 0.f, l1 = 0.f;
    float O[8][4];
    #pragma unroll
    for (int nt = 0; nt < 8; nt++)
        #pragma unroll
        for (int r = 0; r < 4; r++) O[nt][r] = 0.f;

    const int prow = wid * 16 + g;

    const int NT = S_ / 64;
    for (int kc = 0; kc < NT; kc++) {
        const int cur = kc & 1;
        if (kc < NT - 1) {
            const int nxt = cur ^ 1;
            #pragma unroll
            for (int t = 0; t < 2; t++) {
                const int f = t * 256 + tid;
                const int r = f >> 3, c = f & 7;
                cpa16(sb + FK_OFF(nxt) * 2 + r * 144 + c * 16,
                      Kg + (size_t)((kc + 1) * 64 + r) * DH_ + c * 8);
                cpa16(sb + FV_OFF(nxt) * 2 + r * 144 + c * 16,
                      Vt + (size_t)r * S_ + (kc + 1) * 64 + c * 8);
            }
            asm volatile("cp.async.commit_group;");
            asm volatile("cp.async.wait_group 1;");
        } else {
            asm volatile("cp.async.wait_group 0;");
        }
        __syncthreads();

        const unsigned* Kw = reinterpret_cast<const unsigned*>(smh + FK_OFF(cur));
        const unsigned* Vw = reinterpret_cast<const unsigned*>(smh + FV_OFF(cur));

        // ---- S = Q @ K^T  (16 x 64 per warp), base-2 scaled ----
        float Sa[8][4];
        #pragma unroll
        for (int nt = 0; nt < 8; nt++)
            #pragma unroll
            for (int r = 0; r < 4; r++) Sa[nt][r] = 0.f;

        #pragma unroll
        for (int kd = 0; kd < 4; kd++) {
            unsigned Qf[4];
            const int cw = kd * 8 + j;              // word col
            Qf[0] = Qw[prow * 36 + cw];             // row g,   k 2j,2j+1
            Qf[1] = Qw[(prow + 8) * 36 + cw];       // row g+8
            Qf[2] = Qw[prow * 36 + cw + 4];         // row g,   k 2j+8,2j+9
            Qf[3] = Qw[(prow + 8) * 36 + cw + 4];
            #pragma unroll
            for (int nt = 0; nt < 8; nt++) {
                unsigned bf[2];
                bf[0] = Kw[(nt * 8 + g) * 36 + cw];
                bf[1] = Kw[(nt * 8 + g) * 36 + cw + 4];
                mma16(Sa[nt], Qf, bf);
            }
        }

        // ---- mask + tile max ----
        float tm0 = -1e30f, tm1 = -1e30f;
        #pragma unroll
        for (int nt = 0; nt < 8; nt++) {
            const float2 mk = __ldg(reinterpret_cast<const float2*>(
                mrow + kc * 64 + nt * 8 + 2 * j));
            const float mk0 = mk.x * LOG2E, mk1 = mk.y * LOG2E;
            Sa[nt][0] += mk0; Sa[nt][1] += mk1;
            Sa[nt][2] += mk0; Sa[nt][3] += mk1;
            tm0 = fmaxf(tm0, fmaxf(Sa[nt][0], Sa[nt][1]));
            tm1 = fmaxf(tm1, fmaxf(Sa[nt][2], Sa[nt][3]));
        }
        tm0 = fmaxf(tm0, __shfl_xor_sync(0xffffffffu, tm0, 1));
        tm0 = fmaxf(tm0, __shfl_xor_sync(0xffffffffu, tm0, 2));
        tm1 = fmaxf(tm1, __shfl_xor_sync(0xffffffffu, tm1, 1));
        tm1 = fmaxf(tm1, __shfl_xor_sync(0xffffffffu, tm1, 2));

        const float nm0 = fmaxf(m0, tm0), nm1 = fmaxf(m1, tm1);
        const float al0 = ex2(m0 - nm0), al1 = ex2(m1 - nm1);
        m0 = nm0; m1 = nm1;

        // ---- P = 2^(S - m) in place; row sums ----
        float rs0 = 0.f, rs1 = 0.f;
        #pragma unroll
        for (int nt = 0; nt < 8; nt++) {
            Sa[nt][0] = ex2(Sa[nt][0] - nm0);
            Sa[nt][1] = ex2(Sa[nt][1] - nm0);
            Sa[nt][2] = ex2(Sa[nt][2] - nm1);
            Sa[nt][3] = ex2(Sa[nt][3] - nm1);
            rs0 += Sa[nt][0] + Sa[nt][1];
            rs1 += Sa[nt][2] + Sa[nt][3];
        }
        rs0 += __shfl_xor_sync(0xffffffffu, rs0, 1);
        rs0 += __shfl_xor_sync(0xffffffffu, rs0, 2);
        rs1 += __shfl_xor_sync(0xffffffffu, rs1, 1);
        rs1 += __shfl_xor_sync(0xffffffffu, rs1, 2);
        l0 = l0 * al0 + rs0;
        l1 = l1 * al1 + rs1;

        #pragma unroll
        for (int nt = 0; nt < 8; nt++) {
            O[nt][0] *= al0; O[nt][1] *= al0;
            O[nt][2] *= al1; O[nt][3] *= al1;
        }

        // ---- O += P @ V : C-fragments pack straight into A-fragments ----
        #pragma unroll
        for (int kk = 0; kk < 4; kk++) {
            unsigned Pf[4];
            Pf[0] = packh2(Sa[2 * kk][0],     Sa[2 * kk][1]);      // row g,   k 2j,2j+1
            Pf[1] = packh2(Sa[2 * kk][2],     Sa[2 * kk][3]);      // row g+8
            Pf[2] = packh2(Sa[2 * kk + 1][0], Sa[2 * kk + 1][1]);  // row g,   k 2j+8
            Pf[3] = packh2(Sa[2 * kk + 1][2], Sa[2 * kk + 1][3]);
            #pragma unroll
            for (int nt = 0; nt < 8; nt++) {
                unsigned bf[2];
                bf[0] = Vw[(nt * 8 + g) * 36 + kk * 8 + j];
                bf[1] = Vw[(nt * 8 + g) * 36 + kk * 8 + j + 4];
                mma16(O[nt], Pf, bf);
            }
        }
        __syncthreads();   // all reads of buf[cur] done before next prefetch
    }

    // Epilogue: normalize, write merged-head [B,S,H].
    const float inv0 = 1.f / l0, inv1 = 1.f / l1;
    const int r0 = qbase + prow;
    #pragma unroll
    for (int nt = 0; nt < 8; nt++) {
        const int c = h * 64 + nt * 8 + 2 * j;
        float2 o0, o1;
        o0.x = O[nt][0] * inv0; o0.y = O[nt][1] * inv0;
        o1.x = O[nt][2] * inv1; o1.y = O[nt][3] * inv1;
        *reinterpret_cast<float2*>(out + ((size_t)bb * S_ + r0) * H_ + c) = o0;
        *reinterpret_cast<float2*>(out + ((size_t)bb * S_ + r0 + 8) * H_ + c) = o1;
    }
}

extern "C" void kernel_launch(void* const* d_in, const int* in_sizes, int n_in,
                              void* d_out, int out_size)
{
    const float* hs   = (const float*)d_in[0];
    const float* mask = (const float*)d_in[1];
    const float* Wq   = (const float*)d_in[2];
    const float* bq   = (const float*)d_in[3];
    const float* Wk   = (const float*)d_in[4];
    const float* bk   = (const float*)d_in[5];
    const float* Wv   = (const float*)d_in[6];
    const float* bv   = (const float*)d_in[7];
    float* out = (float*)d_out;

    const int smem_gemm = (2 * 128 * AST + 2 * 32 * BST) * 4;
    cudaFuncSetAttribute(qkv_gemm, cudaFuncAttributeMaxDynamicSharedMemorySize, smem_gemm);
    dim3 g1(H_ / 128, (B_ * S_) / 128, 3);
    qkv_gemm<<<g1, 256, smem_gemm>>>(hs, Wq, bq, Wk, bk, Wv, bv);

    cudaFuncSetAttribute(flash_attn_h, cudaFuncAttributeMaxDynamicSharedMemorySize, F_TOTAL_BYTES);
    dim3 g2(S_ / 128, NH_, B_);
    flash_attn_h<<<g2, 256, F_TOTAL_BYTES>>>(mask, out);
}

// round 9
// speedup vs baseline: 2.1023x; 1.4691x over previous
#include <cuda_runtime.h>
#include <cuda_fp16.h>
#include <cstdint>

#define B_  2
#define S_  2048
#define H_  1024
#define NH_ 16
#define DH_ 64
#define LOG2E 1.4426950408889634f

// Scratch (fp16): Q,K in [B,NH,S,DH]; V TRANSPOSED per head [B,NH,DH,S].
__device__ __align__(16) __half g_q[(size_t)B_ * NH_ * S_ * DH_];
__device__ __align__(16) __half g_k[(size_t)B_ * NH_ * S_ * DH_];
__device__ __align__(16) __half g_v[(size_t)B_ * NH_ * S_ * DH_];
// Pre-pass scratch: fp16 hidden states + fp16 transposed weights [3][n][k].
__device__ __align__(16) __half g_hsh[(size_t)B_ * S_ * H_];
__device__ __align__(16) __half g_wt[(size_t)3 * H_ * H_];

__device__ __forceinline__ float ex2(float x) {
    float y;
    asm("ex2.approx.ftz.f32 %0, %1;" : "=f"(y) : "f"(x));
    return y;
}
__device__ __forceinline__ unsigned packh2(float lo, float hi) {
    unsigned r;
    asm("cvt.rn.f16x2.f32 %0, %1, %2;" : "=r"(r) : "f"(hi), "f"(lo));
    return r;
}
__device__ __forceinline__ void cpa16(unsigned dst, const void* src) {
    asm volatile("cp.async.cg.shared.global [%0], [%1], 16;" :: "r"(dst), "l"(src));
}
// fp16 m16n8k16, fp32 accumulate
__device__ __forceinline__ void mma16(float* d, const unsigned* a, const unsigned* b) {
    asm volatile(
        "mma.sync.aligned.m16n8k16.row.col.f32.f16.f16.f32 "
        "{%0,%1,%2,%3}, {%4,%5,%6,%7}, {%8,%9}, {%0,%1,%2,%3};"
        : "+f"(d[0]), "+f"(d[1]), "+f"(d[2]), "+f"(d[3])
        : "r"(a[0]), "r"(a[1]), "r"(a[2]), "r"(a[3]), "r"(b[0]), "r"(b[1]));
}

// ---------------------------------------------------------------------------
// Pre-pass 1: hs fp32 -> fp16.
// ---------------------------------------------------------------------------
__global__ __launch_bounds__(256) void cvt_hs(const float* __restrict__ hs) {
    const size_t i = ((size_t)blockIdx.x * 256 + threadIdx.x) * 8;
    float4 v0 = *reinterpret_cast<const float4*>(hs + i);
    float4 v1 = *reinterpret_cast<const float4*>(hs + i + 4);
    __half2 h[4] = { __floats2half2_rn(v0.x, v0.y), __floats2half2_rn(v0.z, v0.w),
                     __floats2half2_rn(v1.x, v1.y), __floats2half2_rn(v1.z, v1.w) };
    *reinterpret_cast<uint4*>(g_hsh + i) = *reinterpret_cast<uint4*>(h);
}

// ---------------------------------------------------------------------------
// Pre-pass 2: W fp32 [k][n] -> fp16 transposed g_wt[z][n][k].
// ---------------------------------------------------------------------------
__global__ __launch_bounds__(256) void wtrans(
    const float* __restrict__ Wq, const float* __restrict__ Wk,
    const float* __restrict__ Wv)
{
    __shared__ float t[32][33];
    const int z = blockIdx.z;
    const float* W = (z == 0) ? Wq : (z == 1) ? Wk : Wv;
    const int tx = threadIdx.x & 31, ty = threadIdx.x >> 5;
    #pragma unroll
    for (int r = 0; r < 4; r++) {
        const int k = blockIdx.y * 32 + ty + r * 8;
        const int n = blockIdx.x * 32 + tx;
        t[ty + r * 8][tx] = W[(size_t)k * H_ + n];
    }
    __syncthreads();
    __half* Wt = g_wt + (size_t)z * H_ * H_;
    #pragma unroll
    for (int r = 0; r < 4; r++) {
        const int n = blockIdx.x * 32 + ty + r * 8;
        const int k = blockIdx.y * 32 + tx;
        Wt[(size_t)n * H_ + k] = __float2half_rn(t[tx][ty + r * 8]);
    }
}

// ---------------------------------------------------------------------------
// Kernel 1: QKV projection, fp16 m16n8k16, cp.async double-buffered.
// Block tile 128m x 128n, k-chunk 32. Warp grid 2(m) x 4(n), warp tile 64x32.
// ---------------------------------------------------------------------------
#define GST 20   // smem words per 32-half row (16 data + 4 pad)

__global__ __launch_bounds__(256, 2) void qkv_gemm_h(
    const float* __restrict__ bq, const float* __restrict__ bk,
    const float* __restrict__ bv)
{
    extern __shared__ unsigned gsm[];
    unsigned* Asb[2] = { gsm, gsm + 2560 };
    unsigned* Bsb[2] = { gsm + 5120, gsm + 7680 };
    const uint32_t sA[2] = { (uint32_t)__cvta_generic_to_shared(Asb[0]),
                             (uint32_t)__cvta_generic_to_shared(Asb[1]) };
    const uint32_t sB[2] = { (uint32_t)__cvta_generic_to_shared(Bsb[0]),
                             (uint32_t)__cvta_generic_to_shared(Bsb[1]) };

    const int z = blockIdx.z;
    const __half* Ag = g_hsh;
    const __half* Bg = g_wt + (size_t)z * H_ * H_;
    const float* bias = (z == 0) ? bq : (z == 1) ? bk : bv;
    const float oscale = (z == 0) ? 0.125f * LOG2E : 1.0f;

    const int tid  = threadIdx.x;
    const int lane = tid & 31;
    const int wid  = tid >> 5;
    const int g = lane >> 2, j = lane & 3;
    const int wm = wid >> 2, wn = wid & 3;

    const int m0 = blockIdx.y * 128;
    const int n0 = blockIdx.x * 128;

    float acc[4][4][4];
    #pragma unroll
    for (int mt = 0; mt < 4; mt++)
        #pragma unroll
        for (int nt = 0; nt < 4; nt++)
            #pragma unroll
            for (int r = 0; r < 4; r++) acc[mt][nt][r] = 0.f;

    #pragma unroll
    for (int t = 0; t < 2; t++) {
        const int idx = t * 256 + tid;
        const int r = idx >> 2, c = idx & 3;
        cpa16(sA[0] + (r * GST + c * 4) * 4, Ag + (size_t)(m0 + r) * H_ + c * 8);
        cpa16(sB[0] + (r * GST + c * 4) * 4, Bg + (size_t)(n0 + r) * H_ + c * 8);
    }
    asm volatile("cp.async.commit_group;");

    const int NC = H_ / 32;
    for (int kc = 0; kc < NC; kc++) {
        const int cur = kc & 1;
        if (kc < NC - 1) {
            const int nxt = cur ^ 1;
            const int k0 = (kc + 1) * 32;
            #pragma unroll
            for (int t = 0; t < 2; t++) {
                const int idx = t * 256 + tid;
                const int r = idx >> 2, c = idx & 3;
                cpa16(sA[nxt] + (r * GST + c * 4) * 4,
                      Ag + (size_t)(m0 + r) * H_ + k0 + c * 8);
                cpa16(sB[nxt] + (r * GST + c * 4) * 4,
                      Bg + (size_t)(n0 + r) * H_ + k0 + c * 8);
            }
            asm volatile("cp.async.commit_group;");
            asm volatile("cp.async.wait_group 1;");
        } else {
            asm volatile("cp.async.wait_group 0;");
        }
        __syncthreads();

        const unsigned* As = Asb[cur];
        const unsigned* Bs = Bsb[cur];
        #pragma unroll
        for (int kd = 0; kd < 2; kd++) {
            const int cw = kd * 8 + j;
            unsigned af[4][4];
            #pragma unroll
            for (int mt = 0; mt < 4; mt++) {
                const int row = wm * 64 + mt * 16 + g;
                af[mt][0] = As[row * GST + cw];
                af[mt][1] = As[(row + 8) * GST + cw];
                af[mt][2] = As[row * GST + cw + 4];
                af[mt][3] = As[(row + 8) * GST + cw + 4];
            }
            #pragma unroll
            for (int nt = 0; nt < 4; nt++) {
                const int row = wn * 32 + nt * 8 + g;
                unsigned bf[2];
                bf[0] = Bs[row * GST + cw];
                bf[1] = Bs[row * GST + cw + 4];
                #pragma unroll
                for (int mt = 0; mt < 4; mt++)
                    mma16(acc[mt][nt], af[mt], bf);
            }
        }
        __syncthreads();
    }

    const int bb = m0 >> 11;
    const int s0 = m0 & (S_ - 1);

    if (z != 2) {
        __half* outp = (z == 0) ? g_q : g_k;
        #pragma unroll
        for (int mt = 0; mt < 4; mt++) {
            #pragma unroll
            for (int nt = 0; nt < 4; nt++) {
                const int c = n0 + wn * 32 + nt * 8 + 2 * j;
                const int h = c >> 6, d = c & 63;
                const float b0 = bias[c], b1 = bias[c + 1];
                #pragma unroll
                for (int hf = 0; hf < 2; hf++) {
                    const int m = m0 + wm * 64 + mt * 16 + g + hf * 8;
                    const int s = m & (S_ - 1);
                    __half2 o = __floats2half2_rn(
                        (acc[mt][nt][hf * 2 + 0] + b0) * oscale,
                        (acc[mt][nt][hf * 2 + 1] + b1) * oscale);
                    *reinterpret_cast<__half2*>(
                        outp + (((size_t)bb * NH_ + h) * S_ + s) * DH_ + d) = o;
                }
            }
        }
    } else {
        // V: stage transposed tile in smem, then coalesced 16B writes.
        __half* st = reinterpret_cast<__half*>(gsm);   // [128 n][136 m halves]
        #pragma unroll
        for (int mt = 0; mt < 4; mt++) {
            #pragma unroll
            for (int nt = 0; nt < 4; nt++) {
                const int cl = wn * 32 + nt * 8 + 2 * j;
                const float b0 = bias[n0 + cl], b1 = bias[n0 + cl + 1];
                #pragma unroll
                for (int hf = 0; hf < 2; hf++) {
                    const int ml = wm * 64 + mt * 16 + g + hf * 8;
                    st[cl * 136 + ml]       = __float2half_rn(acc[mt][nt][hf * 2 + 0] + b0);
                    st[(cl + 1) * 136 + ml] = __float2half_rn(acc[mt][nt][hf * 2 + 1] + b1);
                }
            }
        }
        __syncthreads();
        // FIX (R8 bug): full tile is 128 rows x 128 halves = 2048 x 16B chunks.
        #pragma unroll
        for (int t = 0; t < 8; t++) {
            const int idx = t * 256 + tid;          // 2048 x 16B
            const int row = idx >> 4, c8 = idx & 15;
            uint4 v = *reinterpret_cast<uint4*>(&st[row * 136 + c8 * 8]);
            const int c = n0 + row;
            const int h = c >> 6, d = c & 63;
            *reinterpret_cast<uint4*>(
                g_v + (((size_t)bb * NH_ + h) * DH_ + d) * S_ + s0 + c8 * 8) = v;
        }
    }
}

// ---------------------------------------------------------------------------
// Kernel 2: fp16 flash attention (m16n8k16) — unchanged (proven 152 us).
// ---------------------------------------------------------------------------
#define FST 72
#define FQ_OFF 0
#define FK_OFF(b) (9216 + (b) * 4608)
#define FV_OFF(b) (18432 + (b) * 4608)
#define F_TOTAL_BYTES 55296

__global__ __launch_bounds__(256, 2) void flash_attn_h(
    const float* __restrict__ mask, float* __restrict__ out)
{
    extern __shared__ __half smh[];
    const uint32_t sb = (uint32_t)__cvta_generic_to_shared(smh);
    const unsigned* Qw = reinterpret_cast<const unsigned*>(smh + FQ_OFF);

    const int tid  = threadIdx.x;
    const int lane = tid & 31;
    const int wid  = tid >> 5;
    const int g = lane >> 2, j = lane & 3;

    const int qbase = blockIdx.x * 128;
    const int h = blockIdx.y, bb = blockIdx.z;
    const __half* Qg = g_q + ((size_t)bb * NH_ + h) * S_ * DH_;
    const __half* Kg = g_k + ((size_t)bb * NH_ + h) * S_ * DH_;
    const __half* Vt = g_v + ((size_t)bb * NH_ + h) * DH_ * S_;
    const float* mrow = mask + (size_t)bb * S_;

    #pragma unroll
    for (int t = 0; t < 4; t++) {
        const int f = t * 256 + tid;
        const int r = f >> 3, c = f & 7;
        cpa16(sb + FQ_OFF * 2 + r * 144 + c * 16, Qg + (size_t)(qbase + r) * DH_ + c * 8);
    }
    #pragma unroll
    for (int t = 0; t < 2; t++) {
        const int f = t * 256 + tid;
        const int r = f >> 3, c = f & 7;
        cpa16(sb + FK_OFF(0) * 2 + r * 144 + c * 16, Kg + (size_t)r * DH_ + c * 8);
        cpa16(sb + FV_OFF(0) * 2 + r * 144 + c * 16, Vt + (size_t)r * S_ + c * 8);
    }
    asm volatile("cp.async.commit_group;");

    float m0 = -1e30f, m1 = -1e30f, l0 = 0.f, l1 = 0.f;
    float O[8][4];
    #pragma unroll
    for (int nt = 0; nt < 8; nt++)
        #pragma unroll
        for (int r = 0; r < 4; r++) O[nt][r] = 0.f;

    const int prow = wid * 16 + g;

    const int NT = S_ / 64;
    for (int kc = 0; kc < NT; kc++) {
        const int cur = kc & 1;
        if (kc < NT - 1) {
            const int nxt = cur ^ 1;
            #pragma unroll
            for (int t = 0; t < 2; t++) {
                const int f = t * 256 + tid;
                const int r = f >> 3, c = f & 7;
                cpa16(sb + FK_OFF(nxt) * 2 + r * 144 + c * 16,
                      Kg + (size_t)((kc + 1) * 64 + r) * DH_ + c * 8);
                cpa16(sb + FV_OFF(nxt) * 2 + r * 144 + c * 16,
                      Vt + (size_t)r * S_ + (kc + 1) * 64 + c * 8);
            }
            asm volatile("cp.async.commit_group;");
            asm volatile("cp.async.wait_group 1;");
        } else {
            asm volatile("cp.async.wait_group 0;");
        }
        __syncthreads();

        const unsigned* Kw = reinterpret_cast<const unsigned*>(smh + FK_OFF(cur));
        const unsigned* Vw = reinterpret_cast<const unsigned*>(smh + FV_OFF(cur));

        float Sa[8][4];
        #pragma unroll
        for (int nt = 0; nt < 8; nt++)
            #pragma unroll
            for (int r = 0; r < 4; r++) Sa[nt][r] = 0.f;

        #pragma unroll
        for (int kd = 0; kd < 4; kd++) {
            unsigned Qf[4];
            const int cw = kd * 8 + j;
            Qf[0] = Qw[prow * 36 + cw];
            Qf[1] = Qw[(prow + 8) * 36 + cw];
            Qf[2] = Qw[prow * 36 + cw + 4];
            Qf[3] = Qw[(prow + 8) * 36 + cw + 4];
            #pragma unroll
            for (int nt = 0; nt < 8; nt++) {
                unsigned bf[2];
                bf[0] = Kw[(nt * 8 + g) * 36 + cw];
                bf[1] = Kw[(nt * 8 + g) * 36 + cw + 4];
                mma16(Sa[nt], Qf, bf);
            }
        }

        float tm0 = -1e30f, tm1 = -1e30f;
        #pragma unroll
        for (int nt = 0; nt < 8; nt++) {
            const float2 mk = __ldg(reinterpret_cast<const float2*>(
                mrow + kc * 64 + nt * 8 + 2 * j));
            const float mk0 = mk.x * LOG2E, mk1 = mk.y * LOG2E;
            Sa[nt][0] += mk0; Sa[nt][1] += mk1;
            Sa[nt][2] += mk0; Sa[nt][3] += mk1;
            tm0 = fmaxf(tm0, fmaxf(Sa[nt][0], Sa[nt][1]));
            tm1 = fmaxf(tm1, fmaxf(Sa[nt][2], Sa[nt][3]));
        }
        tm0 = fmaxf(tm0, __shfl_xor_sync(0xffffffffu, tm0, 1));
        tm0 = fmaxf(tm0, __shfl_xor_sync(0xffffffffu, tm0, 2));
        tm1 = fmaxf(tm1, __shfl_xor_sync(0xffffffffu, tm1, 1));
        tm1 = fmaxf(tm1, __shfl_xor_sync(0xffffffffu, tm1, 2));

        const float nm0 = fmaxf(m0, tm0), nm1 = fmaxf(m1, tm1);
        const float al0 = ex2(m0 - nm0), al1 = ex2(m1 - nm1);
        m0 = nm0; m1 = nm1;

        float rs0 = 0.f, rs1 = 0.f;
        #pragma unroll
        for (int nt = 0; nt < 8; nt++) {
            Sa[nt][0] = ex2(Sa[nt][0] - nm0);
            Sa[nt][1] = ex2(Sa[nt][1] - nm0);
            Sa[nt][2] = ex2(Sa[nt][2] - nm1);
            Sa[nt][3] = ex2(Sa[nt][3] - nm1);
            rs0 += Sa[nt][0] + Sa[nt][1];
            rs1 += Sa[nt][2] + Sa[nt][3];
        }
        rs0 += __shfl_xor_sync(0xffffffffu, rs0, 1);
        rs0 += __shfl_xor_sync(0xffffffffu, rs0, 2);
        rs1 += __shfl_xor_sync(0xffffffffu, rs1, 1);
        rs1 += __shfl_xor_sync(0xffffffffu, rs1, 2);
        l0 = l0 * al0 + rs0;
        l1 = l1 * al1 + rs1;

        #pragma unroll
        for (int nt = 0; nt < 8; nt++) {
            O[nt][0] *= al0; O[nt][1] *= al0;
            O[nt][2] *= al1; O[nt][3] *= al1;
        }

        #pragma unroll
        for (int kk = 0; kk < 4; kk++) {
            unsigned Pf[4];
            Pf[0] = packh2(Sa[2 * kk][0],     Sa[2 * kk][1]);
            Pf[1] = packh2(Sa[2 * kk][2],     Sa[2 * kk][3]);
            Pf[2] = packh2(Sa[2 * kk + 1][0], Sa[2 * kk + 1][1]);
            Pf[3] = packh2(Sa[2 * kk + 1][2], Sa[2 * kk + 1][3]);
            #pragma unroll
            for (int nt = 0; nt < 8; nt++) {
                unsigned bf[2];
                bf[0] = Vw[(nt * 8 + g) * 36 + kk * 8 + j];
                bf[1] = Vw[(nt * 8 + g) * 36 + kk * 8 + j + 4];
                mma16(O[nt], Pf, bf);
            }
        }
        __syncthreads();
    }

    const float inv0 = 1.f / l0, inv1 = 1.f / l1;
    const int r0 = qbase + prow;
    #pragma unroll
    for (int nt = 0; nt < 8; nt++) {
        const int c = h * 64 + nt * 8 + 2 * j;
        float2 o0, o1;
        o0.x = O[nt][0] * inv0; o0.y = O[nt][1] * inv0;
        o1.x = O[nt][2] * inv1; o1.y = O[nt][3] * inv1;
        *reinterpret_cast<float2*>(out + ((size_t)bb * S_ + r0) * H_ + c) = o0;
        *reinterpret_cast<float2*>(out + ((size_t)bb * S_ + r0 + 8) * H_ + c) = o1;
    }
}

extern "C" void kernel_launch(void* const* d_in, const int* in_sizes, int n_in,
                              void* d_out, int out_size)
{
    const float* hs   = (const float*)d_in[0];
    const float* mask = (const float*)d_in[1];
    const float* Wq   = (const float*)d_in[2];
    const float* bq   = (const float*)d_in[3];
    const float* Wk   = (const float*)d_in[4];
    const float* bk   = (const float*)d_in[5];
    const float* Wv   = (const float*)d_in[6];
    const float* bv   = (const float*)d_in[7];
    float* out = (float*)d_out;

    cvt_hs<<<(B_ * S_ * H_) / (256 * 8), 256>>>(hs);
    dim3 gw(H_ / 32, H_ / 32, 3);
    wtrans<<<gw, 256>>>(Wq, Wk, Wv);

    const int smem_gemm = 10240 * 4;   // 40 KB
    cudaFuncSetAttribute(qkv_gemm_h, cudaFuncAttributeMaxDynamicSharedMemorySize, smem_gemm);
    dim3 g1(H_ / 128, (B_ * S_) / 128, 3);
    qkv_gemm_h<<<g1, 256, smem_gemm>>>(bq, bk, bv);

    cudaFuncSetAttribute(flash_attn_h, cudaFuncAttributeMaxDynamicSharedMemorySize, F_TOTAL_BYTES);
    dim3 g2(S_ / 128, NH_, B_);
    flash_attn_h<<<g2, 256, F_TOTAL_BYTES>>>(mask, out);
}

// round 10
// speedup vs baseline: 2.4671x; 1.1735x over previous
#include <cuda_runtime.h>
#include <cuda_fp16.h>
#include <cstdint>

#define B_  2
#define S_  2048
#define H_  1024
#define NH_ 16
#define DH_ 64
#define LOG2E 1.4426950408889634f

// Scratch (fp16): Q,K in [B,NH,S,DH]; V TRANSPOSED per head [B,NH,DH,S].
__device__ __align__(16) __half g_q[(size_t)B_ * NH_ * S_ * DH_];
__device__ __align__(16) __half g_k[(size_t)B_ * NH_ * S_ * DH_];
__device__ __align__(16) __half g_v[(size_t)B_ * NH_ * S_ * DH_];
// Pre-pass scratch: fp16 hidden states + fp16 transposed weights [3][n][k].
__device__ __align__(16) __half g_hsh[(size_t)B_ * S_ * H_];
__device__ __align__(16) __half g_wt[(size_t)3 * H_ * H_];

__device__ __forceinline__ float ex2(float x) {
    float y;
    asm("ex2.approx.ftz.f32 %0, %1;" : "=f"(y) : "f"(x));
    return y;
}
__device__ __forceinline__ unsigned packh2(float lo, float hi) {
    unsigned r;
    asm("cvt.rn.f16x2.f32 %0, %1, %2;" : "=r"(r) : "f"(hi), "f"(lo));
    return r;
}
__device__ __forceinline__ void cpa16(unsigned dst, const void* src) {
    asm volatile("cp.async.cg.shared.global [%0], [%1], 16;" :: "r"(dst), "l"(src));
}
// fp16 m16n8k16, fp32 accumulate
__device__ __forceinline__ void mma16(float* d, const unsigned* a, const unsigned* b) {
    asm volatile(
        "mma.sync.aligned.m16n8k16.row.col.f32.f16.f16.f32 "
        "{%0,%1,%2,%3}, {%4,%5,%6,%7}, {%8,%9}, {%0,%1,%2,%3};"
        : "+f"(d[0]), "+f"(d[1]), "+f"(d[2]), "+f"(d[3])
        : "r"(a[0]), "r"(a[1]), "r"(a[2]), "r"(a[3]), "r"(b[0]), "r"(b[1]));
}
// ldmatrix x4: four 8x8 b16 tiles, one row-address per lane.
__device__ __forceinline__ void ldsm4(unsigned* r, uint32_t addr) {
    asm volatile("ldmatrix.sync.aligned.m8n8.x4.shared.b16 {%0,%1,%2,%3}, [%4];"
        : "=r"(r[0]), "=r"(r[1]), "=r"(r[2]), "=r"(r[3]) : "r"(addr));
}

// ---------------------------------------------------------------------------
// Pre-pass 1: hs fp32 -> fp16.
// ---------------------------------------------------------------------------
__global__ __launch_bounds__(256) void cvt_hs(const float* __restrict__ hs) {
    const size_t i = ((size_t)blockIdx.x * 256 + threadIdx.x) * 8;
    float4 v0 = *reinterpret_cast<const float4*>(hs + i);
    float4 v1 = *reinterpret_cast<const float4*>(hs + i + 4);
    __half2 h[4] = { __floats2half2_rn(v0.x, v0.y), __floats2half2_rn(v0.z, v0.w),
                     __floats2half2_rn(v1.x, v1.y), __floats2half2_rn(v1.z, v1.w) };
    *reinterpret_cast<uint4*>(g_hsh + i) = *reinterpret_cast<uint4*>(h);
}

// ---------------------------------------------------------------------------
// Pre-pass 2: W fp32 [k][n] -> fp16 transposed g_wt[z][n][k].
// ---------------------------------------------------------------------------
__global__ __launch_bounds__(256) void wtrans(
    const float* __restrict__ Wq, const float* __restrict__ Wk,
    const float* __restrict__ Wv)
{
    __shared__ float t[32][33];
    const int z = blockIdx.z;
    const float* W = (z == 0) ? Wq : (z == 1) ? Wk : Wv;
    const int tx = threadIdx.x & 31, ty = threadIdx.x >> 5;
    #pragma unroll
    for (int r = 0; r < 4; r++) {
        const int k = blockIdx.y * 32 + ty + r * 8;
        const int n = blockIdx.x * 32 + tx;
        t[ty + r * 8][tx] = W[(size_t)k * H_ + n];
    }
    __syncthreads();
    __half* Wt = g_wt + (size_t)z * H_ * H_;
    #pragma unroll
    for (int r = 0; r < 4; r++) {
        const int n = blockIdx.x * 32 + ty + r * 8;
        const int k = blockIdx.y * 32 + tx;
        Wt[(size_t)n * H_ + k] = __float2half_rn(t[tx][ty + r * 8]);
    }
}

// ---------------------------------------------------------------------------
// Kernel 1: QKV projection, fp16 m16n8k16 + ldmatrix, cp.async double-buffered.
// Block tile 128m x 128n, k-chunk 32. Warp grid 2(m) x 4(n), warp tile 64x32.
// ---------------------------------------------------------------------------
#define GST 20   // smem words per 32-half row (80 B stride; ldmatrix-conflict-free)

__global__ __launch_bounds__(256, 2) void qkv_gemm_h(
    const float* __restrict__ bq, const float* __restrict__ bk,
    const float* __restrict__ bv)
{
    extern __shared__ unsigned gsm[];
    unsigned* Asb[2] = { gsm, gsm + 2560 };
    unsigned* Bsb[2] = { gsm + 5120, gsm + 7680 };
    const uint32_t sA[2] = { (uint32_t)__cvta_generic_to_shared(Asb[0]),
                             (uint32_t)__cvta_generic_to_shared(Asb[1]) };
    const uint32_t sB[2] = { (uint32_t)__cvta_generic_to_shared(Bsb[0]),
                             (uint32_t)__cvta_generic_to_shared(Bsb[1]) };

    const int z = blockIdx.z;
    const __half* Ag = g_hsh;
    const __half* Bg = g_wt + (size_t)z * H_ * H_;
    const float* bias = (z == 0) ? bq : (z == 1) ? bk : bv;
    const float oscale = (z == 0) ? 0.125f * LOG2E : 1.0f;

    const int tid  = threadIdx.x;
    const int lane = tid & 31;
    const int wid  = tid >> 5;
    const int g = lane >> 2, j = lane & 3;
    const int wm = wid >> 2, wn = wid & 3;

    const int m0 = blockIdx.y * 128;
    const int n0 = blockIdx.x * 128;

    // ldmatrix lane offsets (bytes). A tile rows stride 80 B.
    const int lm = lane >> 3;
    const uint32_t a_lane = (uint32_t)((wm * 64 + (lane & 7) + (lm & 1) * 8) * 80
                                       + (lane >> 4) * 16);
    const uint32_t b_lane = (uint32_t)((wn * 32 + (lm >> 1) * 8 + (lane & 7)) * 80
                                       + (lm & 1) * 16);

    float acc[4][4][4];
    #pragma unroll
    for (int mt = 0; mt < 4; mt++)
        #pragma unroll
        for (int nt = 0; nt < 4; nt++)
            #pragma unroll
            for (int r = 0; r < 4; r++) acc[mt][nt][r] = 0.f;

    #pragma unroll
    for (int t = 0; t < 2; t++) {
        const int idx = t * 256 + tid;
        const int r = idx >> 2, c = idx & 3;
        cpa16(sA[0] + (r * GST + c * 4) * 4, Ag + (size_t)(m0 + r) * H_ + c * 8);
        cpa16(sB[0] + (r * GST + c * 4) * 4, Bg + (size_t)(n0 + r) * H_ + c * 8);
    }
    asm volatile("cp.async.commit_group;");

    const int NC = H_ / 32;
    for (int kc = 0; kc < NC; kc++) {
        const int cur = kc & 1;
        if (kc < NC - 1) {
            const int nxt = cur ^ 1;
            const int k0 = (kc + 1) * 32;
            #pragma unroll
            for (int t = 0; t < 2; t++) {
                const int idx = t * 256 + tid;
                const int r = idx >> 2, c = idx & 3;
                cpa16(sA[nxt] + (r * GST + c * 4) * 4,
                      Ag + (size_t)(m0 + r) * H_ + k0 + c * 8);
                cpa16(sB[nxt] + (r * GST + c * 4) * 4,
                      Bg + (size_t)(n0 + r) * H_ + k0 + c * 8);
            }
            asm volatile("cp.async.commit_group;");
            asm volatile("cp.async.wait_group 1;");
        } else {
            asm volatile("cp.async.wait_group 0;");
        }
        __syncthreads();

        const uint32_t ab = sA[cur] + a_lane;
        const uint32_t bb2 = sB[cur] + b_lane;
        #pragma unroll
        for (int kd = 0; kd < 2; kd++) {
            unsigned af[4][4];
            #pragma unroll
            for (int mt = 0; mt < 4; mt++)
                ldsm4(af[mt], ab + mt * 16 * 80 + kd * 32);
            unsigned bfp[2][4];
            #pragma unroll
            for (int p = 0; p < 2; p++)
                ldsm4(bfp[p], bb2 + p * 16 * 80 + kd * 32);
            #pragma unroll
            for (int p = 0; p < 2; p++)
                #pragma unroll
                for (int mt = 0; mt < 4; mt++) {
                    mma16(acc[mt][2 * p],     af[mt], &bfp[p][0]);
                    mma16(acc[mt][2 * p + 1], af[mt], &bfp[p][2]);
                }
        }
        __syncthreads();
    }

    const int bb = m0 >> 11;
    const int s0 = m0 & (S_ - 1);

    if (z != 2) {
        __half* outp = (z == 0) ? g_q : g_k;
        #pragma unroll
        for (int mt = 0; mt < 4; mt++) {
            #pragma unroll
            for (int nt = 0; nt < 4; nt++) {
                const int c = n0 + wn * 32 + nt * 8 + 2 * j;
                const int h = c >> 6, d = c & 63;
                const float b0 = bias[c], b1 = bias[c + 1];
                #pragma unroll
                for (int hf = 0; hf < 2; hf++) {
                    const int m = m0 + wm * 64 + mt * 16 + g + hf * 8;
                    const int s = m & (S_ - 1);
                    __half2 o = __floats2half2_rn(
                        (acc[mt][nt][hf * 2 + 0] + b0) * oscale,
                        (acc[mt][nt][hf * 2 + 1] + b1) * oscale);
                    *reinterpret_cast<__half2*>(
                        outp + (((size_t)bb * NH_ + h) * S_ + s) * DH_ + d) = o;
                }
            }
        }
    } else {
        // V: stage transposed tile in smem, then coalesced 16B writes.
        __half* st = reinterpret_cast<__half*>(gsm);   // [128 n][136 m halves]
        #pragma unroll
        for (int mt = 0; mt < 4; mt++) {
            #pragma unroll
            for (int nt = 0; nt < 4; nt++) {
                const int cl = wn * 32 + nt * 8 + 2 * j;
                const float b0 = bias[n0 + cl], b1 = bias[n0 + cl + 1];
                #pragma unroll
                for (int hf = 0; hf < 2; hf++) {
                    const int ml = wm * 64 + mt * 16 + g + hf * 8;
                    st[cl * 136 + ml]       = __float2half_rn(acc[mt][nt][hf * 2 + 0] + b0);
                    st[(cl + 1) * 136 + ml] = __float2half_rn(acc[mt][nt][hf * 2 + 1] + b1);
                }
            }
        }
        __syncthreads();
        #pragma unroll
        for (int t = 0; t < 8; t++) {
            const int idx = t * 256 + tid;          // 2048 x 16B
            const int row = idx >> 4, c8 = idx & 15;
            uint4 v = *reinterpret_cast<uint4*>(&st[row * 136 + c8 * 8]);
            const int c = n0 + row;
            const int h = c >> 6, d = c & 63;
            *reinterpret_cast<uint4*>(
                g_v + (((size_t)bb * NH_ + h) * DH_ + d) * S_ + s0 + c8 * 8) = v;
        }
    }
}

// ---------------------------------------------------------------------------
// Kernel 2: fp16 flash attention, m16n8k16 + ldmatrix. Mask staged in smem
// (pre-scaled by log2e). Stride 144 B — ldmatrix conflict-free.
// ---------------------------------------------------------------------------
#define FQ_OFF 0
#define FK_OFF(b) (9216 + (b) * 4608)
#define FV_OFF(b) (18432 + (b) * 4608)
#define FM_OFF 27648                 // halves; mask float[2048] lives here
#define F_TOTAL_BYTES (55296 + 8192)

__global__ __launch_bounds__(256, 2) void flash_attn_h(
    const float* __restrict__ mask, float* __restrict__ out)
{
    extern __shared__ __half smh[];
    const uint32_t sb = (uint32_t)__cvta_generic_to_shared(smh);
    float* msks = reinterpret_cast<float*>(smh + FM_OFF);

    const int tid  = threadIdx.x;
    const int lane = tid & 31;
    const int wid  = tid >> 5;
    const int g = lane >> 2, j = lane & 3;

    const int qbase = blockIdx.x * 128;
    const int h = blockIdx.y, bb = blockIdx.z;
    const __half* Qg = g_q + ((size_t)bb * NH_ + h) * S_ * DH_;
    const __half* Kg = g_k + ((size_t)bb * NH_ + h) * S_ * DH_;
    const __half* Vt = g_v + ((size_t)bb * NH_ + h) * DH_ * S_;
    const float* mrow = mask + (size_t)bb * S_;

    // Stage mask (x log2e) into smem: 512 float4.
    #pragma unroll
    for (int t = 0; t < 2; t++) {
        const int i = t * 256 + tid;
        float4 mv = *reinterpret_cast<const float4*>(mrow + i * 4);
        mv.x *= LOG2E; mv.y *= LOG2E; mv.z *= LOG2E; mv.w *= LOG2E;
        *reinterpret_cast<float4*>(msks + i * 4) = mv;
    }

    #pragma unroll
    for (int t = 0; t < 4; t++) {
        const int f = t * 256 + tid;
        const int r = f >> 3, c = f & 7;
        cpa16(sb + FQ_OFF * 2 + r * 144 + c * 16, Qg + (size_t)(qbase + r) * DH_ + c * 8);
    }
    #pragma unroll
    for (int t = 0; t < 2; t++) {
        const int f = t * 256 + tid;
        const int r = f >> 3, c = f & 7;
        cpa16(sb + FK_OFF(0) * 2 + r * 144 + c * 16, Kg + (size_t)r * DH_ + c * 8);
        cpa16(sb + FV_OFF(0) * 2 + r * 144 + c * 16, Vt + (size_t)r * S_ + c * 8);
    }
    asm volatile("cp.async.commit_group;");

    // ldmatrix lane offsets (bytes).
    const int lm = lane >> 3;
    const uint32_t qa = sb + FQ_OFF * 2
        + (uint32_t)((wid * 16 + (lane & 7) + (lm & 1) * 8) * 144 + (lane >> 4) * 16);
    const uint32_t kv_lane = (uint32_t)(((lm >> 1) * 8 + (lane & 7)) * 144 + (lm & 1) * 16);

    float m0 = -1e30f, m1 = -1e30f, l0 = 0.f, l1 = 0.f;
    float O[8][4];
    #pragma unroll
    for (int nt = 0; nt < 8; nt++)
        #pragma unroll
        for (int r = 0; r < 4; r++) O[nt][r] = 0.f;

    const int prow = wid * 16 + g;

    const int NT = S_ / 64;
    for (int kc = 0; kc < NT; kc++) {
        const int cur = kc & 1;
        if (kc < NT - 1) {
            const int nxt = cur ^ 1;
            #pragma unroll
            for (int t = 0; t < 2; t++) {
                const int f = t * 256 + tid;
                const int r = f >> 3, c = f & 7;
                cpa16(sb + FK_OFF(nxt) * 2 + r * 144 + c * 16,
                      Kg + (size_t)((kc + 1) * 64 + r) * DH_ + c * 8);
                cpa16(sb + FV_OFF(nxt) * 2 + r * 144 + c * 16,
                      Vt + (size_t)r * S_ + (kc + 1) * 64 + c * 8);
            }
            asm volatile("cp.async.commit_group;");
            asm volatile("cp.async.wait_group 1;");
        } else {
            asm volatile("cp.async.wait_group 0;");
        }
        __syncthreads();

        const uint32_t kb = sb + FK_OFF(cur) * 2 + kv_lane;
        const uint32_t vb = sb + FV_OFF(cur) * 2 + kv_lane;

        // ---- S = Q @ K^T ----
        float Sa[8][4];
        #pragma unroll
        for (int nt = 0; nt < 8; nt++)
            #pragma unroll
            for (int r = 0; r < 4; r++) Sa[nt][r] = 0.f;

        #pragma unroll
        for (int kd = 0; kd < 4; kd++) {
            unsigned Qf[4];
            ldsm4(Qf, qa + kd * 32);
            #pragma unroll
            for (int p = 0; p < 4; p++) {
                unsigned bf[4];
                ldsm4(bf, kb + p * (16 * 144) + kd * 32);
                mma16(Sa[2 * p],     Qf, &bf[0]);
                mma16(Sa[2 * p + 1], Qf, &bf[2]);
            }
        }

        // ---- mask + tile max ----
        float tm0 = -1e30f, tm1 = -1e30f;
        #pragma unroll
        for (int nt = 0; nt < 8; nt++) {
            const float2 mk = *reinterpret_cast<const float2*>(
                &msks[kc * 64 + nt * 8 + 2 * j]);
            Sa[nt][0] += mk.x; Sa[nt][1] += mk.y;
            Sa[nt][2] += mk.x; Sa[nt][3] += mk.y;
            tm0 = fmaxf(tm0, fmaxf(Sa[nt][0], Sa[nt][1]));
            tm1 = fmaxf(tm1, fmaxf(Sa[nt][2], Sa[nt][3]));
        }
        tm0 = fmaxf(tm0, __shfl_xor_sync(0xffffffffu, tm0, 1));
        tm0 = fmaxf(tm0, __shfl_xor_sync(0xffffffffu, tm0, 2));
        tm1 = fmaxf(tm1, __shfl_xor_sync(0xffffffffu, tm1, 1));
        tm1 = fmaxf(tm1, __shfl_xor_sync(0xffffffffu, tm1, 2));

        const float nm0 = fmaxf(m0, tm0), nm1 = fmaxf(m1, tm1);
        const float al0 = ex2(m0 - nm0), al1 = ex2(m1 - nm1);
        m0 = nm0; m1 = nm1;

        float rs0 = 0.f, rs1 = 0.f;
        #pragma unroll
        for (int nt = 0; nt < 8; nt++) {
            Sa[nt][0] = ex2(Sa[nt][0] - nm0);
            Sa[nt][1] = ex2(Sa[nt][1] - nm0);
            Sa[nt][2] = ex2(Sa[nt][2] - nm1);
            Sa[nt][3] = ex2(Sa[nt][3] - nm1);
            rs0 += Sa[nt][0] + Sa[nt][1];
            rs1 += Sa[nt][2] + Sa[nt][3];
        }
        rs0 += __shfl_xor_sync(0xffffffffu, rs0, 1);
        rs0 += __shfl_xor_sync(0xffffffffu, rs0, 2);
        rs1 += __shfl_xor_sync(0xffffffffu, rs1, 1);
        rs1 += __shfl_xor_sync(0xffffffffu, rs1, 2);
        l0 = l0 * al0 + rs0;
        l1 = l1 * al1 + rs1;

        #pragma unroll
        for (int nt = 0; nt < 8; nt++) {
            O[nt][0] *= al0; O[nt][1] *= al0;
            O[nt][2] *= al1; O[nt][3] *= al1;
        }

        // ---- O += P @ V ----
        #pragma unroll
        for (int kk = 0; kk < 4; kk++) {
            unsigned Pf[4];
            Pf[0] = packh2(Sa[2 * kk][0],     Sa[2 * kk][1]);
            Pf[1] = packh2(Sa[2 * kk][2],     Sa[2 * kk][3]);
            Pf[2] = packh2(Sa[2 * kk + 1][0], Sa[2 * kk + 1][1]);
            Pf[3] = packh2(Sa[2 * kk + 1][2], Sa[2 * kk + 1][3]);
            #pragma unroll
            for (int p = 0; p < 4; p++) {
                unsigned bf[4];
                ldsm4(bf, vb + p * (16 * 144) + kk * 32);
                mma16(O[2 * p],     Pf, &bf[0]);
                mma16(O[2 * p + 1], Pf, &bf[2]);
            }
        }
        __syncthreads();
    }

    const float inv0 = 1.f / l0, inv1 = 1.f / l1;
    const int r0 = qbase + prow;
    #pragma unroll
    for (int nt = 0; nt < 8; nt++) {
        const int c = h * 64 + nt * 8 + 2 * j;
        float2 o0, o1;
        o0.x = O[nt][0] * inv0; o0.y = O[nt][1] * inv0;
        o1.x = O[nt][2] * inv1; o1.y = O[nt][3] * inv1;
        *reinterpret_cast<float2*>(out + ((size_t)bb * S_ + r0) * H_ + c) = o0;
        *reinterpret_cast<float2*>(out + ((size_t)bb * S_ + r0 + 8) * H_ + c) = o1;
    }
}

extern "C" void kernel_launch(void* const* d_in, const int* in_sizes, int n_in,
                              void* d_out, int out_size)
{
    const float* hs   = (const float*)d_in[0];
    const float* mask = (const float*)d_in[1];
    const float* Wq   = (const float*)d_in[2];
    const float* bq   = (const float*)d_in[3];
    const float* Wk   = (const float*)d_in[4];
    const float* bk   = (const float*)d_in[5];
    const float* Wv   = (const float*)d_in[6];
    const float* bv   = (const float*)d_in[7];
    float* out = (float*)d_out;

    cvt_hs<<<(B_ * S_ * H_) / (256 * 8), 256>>>(hs);
    dim3 gw(H_ / 32, H_ / 32, 3);
    wtrans<<<gw, 256>>>(Wq, Wk, Wv);

    const int smem_gemm = 10240 * 4;   // 40 KB
    cudaFuncSetAttribute(qkv_gemm_h, cudaFuncAttributeMaxDynamicSharedMemorySize, smem_gemm);
    dim3 g1(H_ / 128, (B_ * S_) / 128, 3);
    qkv_gemm_h<<<g1, 256, smem_gemm>>>(bq, bk, bv);

    cudaFuncSetAttribute(flash_attn_h, cudaFuncAttributeMaxDynamicSharedMemorySize, F_TOTAL_BYTES);
    dim3 g2(S_ / 128, NH_, B_);
    flash_attn_h<<<g2, 256, F_TOTAL_BYTES>>>(mask, out);
}

// round 12
// speedup vs baseline: 2.5585x; 1.0370x over previous
#include <cuda_runtime.h>
#include <cuda_fp16.h>
#include <cstdint>

#define B_  2
#define S_  2048
#define H_  1024
#define NH_ 16
#define DH_ 64
#define LOG2E 1.4426950408889634f

// Scratch (fp16): Q,K in [B,NH,S,DH]; V TRANSPOSED per head [B,NH,DH,S].
__device__ __align__(16) __half g_q[(size_t)B_ * NH_ * S_ * DH_];
__device__ __align__(16) __half g_k[(size_t)B_ * NH_ * S_ * DH_];
__device__ __align__(16) __half g_v[(size_t)B_ * NH_ * S_ * DH_];
// Pre-pass scratch: fp16 hidden states + fp16 transposed weights [3][n][k].
__device__ __align__(16) __half g_hsh[(size_t)B_ * S_ * H_];
__device__ __align__(16) __half g_wt[(size_t)3 * H_ * H_];

__device__ __forceinline__ unsigned packh2(float lo, float hi) {
    unsigned r;
    asm("cvt.rn.f16x2.f32 %0, %1, %2;" : "=r"(r) : "f"(hi), "f"(lo));
    return r;
}
__device__ __forceinline__ float ex2(float x) {
    float y;
    asm("ex2.approx.ftz.f32 %0, %1;" : "=f"(y) : "f"(x));
    return y;
}
__device__ __forceinline__ unsigned h2exp2(unsigned a) {
    unsigned r;
    asm("ex2.approx.f16x2 %0, %1;" : "=r"(r) : "r"(a));
    return r;
}
__device__ __forceinline__ void cpa16(unsigned dst, const void* src) {
    asm volatile("cp.async.cg.shared.global [%0], [%1], 16;" :: "r"(dst), "l"(src));
}
// fp16 m16n8k16, fp32 accumulate
__device__ __forceinline__ void mma16(float* d, const unsigned* a, const unsigned* b) {
    asm volatile(
        "mma.sync.aligned.m16n8k16.row.col.f32.f16.f16.f32 "
        "{%0,%1,%2,%3}, {%4,%5,%6,%7}, {%8,%9}, {%0,%1,%2,%3};"
        : "+f"(d[0]), "+f"(d[1]), "+f"(d[2]), "+f"(d[3])
        : "r"(a[0]), "r"(a[1]), "r"(a[2]), "r"(a[3]), "r"(b[0]), "r"(b[1]));
}
__device__ __forceinline__ void ldsm4(unsigned* r, uint32_t addr) {
    asm volatile("ldmatrix.sync.aligned.m8n8.x4.shared.b16 {%0,%1,%2,%3}, [%4];"
        : "=r"(r[0]), "=r"(r[1]), "=r"(r[2]), "=r"(r[3]) : "r"(addr));
}

// ---------------------------------------------------------------------------
// Pre-pass 1: hs fp32 -> fp16.
// ---------------------------------------------------------------------------
__global__ __launch_bounds__(256) void cvt_hs(const float* __restrict__ hs) {
    const size_t i = ((size_t)blockIdx.x * 256 + threadIdx.x) * 8;
    float4 v0 = *reinterpret_cast<const float4*>(hs + i);
    float4 v1 = *reinterpret_cast<const float4*>(hs + i + 4);
    __half2 h[4] = { __floats2half2_rn(v0.x, v0.y), __floats2half2_rn(v0.z, v0.w),
                     __floats2half2_rn(v1.x, v1.y), __floats2half2_rn(v1.z, v1.w) };
    *reinterpret_cast<uint4*>(g_hsh + i) = *reinterpret_cast<uint4*>(h);
}

// ---------------------------------------------------------------------------
// Pre-pass 2: W fp32 [k][n] -> fp16 transposed g_wt[z][n][k].
// ---------------------------------------------------------------------------
__global__ __launch_bounds__(256) void wtrans(
    const float* __restrict__ Wq, const float* __restrict__ Wk,
    const float* __restrict__ Wv)
{
    __shared__ float t[32][33];
    const int z = blockIdx.z;
    const float* W = (z == 0) ? Wq : (z == 1) ? Wk : Wv;
    const int tx = threadIdx.x & 31, ty = threadIdx.x >> 5;
    #pragma unroll
    for (int r = 0; r < 4; r++) {
        const int k = blockIdx.y * 32 + ty + r * 8;
        const int n = blockIdx.x * 32 + tx;
        t[ty + r * 8][tx] = W[(size_t)k * H_ + n];
    }
    __syncthreads();
    __half* Wt = g_wt + (size_t)z * H_ * H_;
    #pragma unroll
    for (int r = 0; r < 4; r++) {
        const int n = blockIdx.x * 32 + ty + r * 8;
        const int k = blockIdx.y * 32 + tx;
        Wt[(size_t)n * H_ + k] = __float2half_rn(t[tx][ty + r * 8]);
    }
}

// ---------------------------------------------------------------------------
// Kernel 1: QKV projection, fp16 m16n8k16 + ldmatrix, k-chunk 64,
// cp.async double-buffered. Row stride 144 B (ldmatrix conflict-free).
// Tile = 128 rows x 64 halves = 1024 x 16B chunks per buffer.
// ---------------------------------------------------------------------------
__global__ __launch_bounds__(256, 2) void qkv_gemm_h(
    const float* __restrict__ bq, const float* __restrict__ bk,
    const float* __restrict__ bv)
{
    extern __shared__ unsigned gsm[];
    const uint32_t s0w = (uint32_t)__cvta_generic_to_shared(gsm);
    const uint32_t sA[2] = { s0w,            s0w + 4608 * 4 };
    const uint32_t sB[2] = { s0w + 9216 * 4, s0w + 13824 * 4 };

    const int z = blockIdx.z;
    const __half* Ag = g_hsh;
    const __half* Bg = g_wt + (size_t)z * H_ * H_;
    const float* bias = (z == 0) ? bq : (z == 1) ? bk : bv;
    const float oscale = (z == 0) ? 0.125f * LOG2E : 1.0f;

    const int tid  = threadIdx.x;
    const int lane = tid & 31;
    const int wid  = tid >> 5;
    const int g = lane >> 2, j = lane & 3;
    const int wm = wid >> 2, wn = wid & 3;

    const int m0 = blockIdx.y * 128;
    const int n0 = blockIdx.x * 128;

    const uint32_t a_lane = (uint32_t)((wm * 64 + (lane & 7) + ((lane >> 3) & 1) * 8) * 144
                                       + (lane >> 4) * 16);
    const uint32_t b_lane = (uint32_t)((wn * 32 + ((lane >> 4) & 1) * 8 + (lane & 7)) * 144
                                       + ((lane >> 3) & 1) * 16);

    float acc[4][4][4];
    #pragma unroll
    for (int mt = 0; mt < 4; mt++)
        #pragma unroll
        for (int nt = 0; nt < 4; nt++)
            #pragma unroll
            for (int r = 0; r < 4; r++) acc[mt][nt][r] = 0.f;

    // Prologue: chunk 0 (k=64): 1024 cp16 per tile, 4/thread per tile.
    #pragma unroll
    for (int t = 0; t < 4; t++) {
        const int idx = t * 256 + tid;
        const int r = idx >> 3, c = idx & 7;
        cpa16(sA[0] + r * 144 + c * 16, Ag + (size_t)(m0 + r) * H_ + c * 8);
        cpa16(sB[0] + r * 144 + c * 16, Bg + (size_t)(n0 + r) * H_ + c * 8);
    }
    asm volatile("cp.async.commit_group;");

    const int NC = H_ / 64;   // 16 chunks
    for (int kc = 0; kc < NC; kc++) {
        const int cur = kc & 1;
        if (kc < NC - 1) {
            const int nxt = cur ^ 1;
            const int k0 = (kc + 1) * 64;
            #pragma unroll
            for (int t = 0; t < 4; t++) {
                const int idx = t * 256 + tid;
                const int r = idx >> 3, c = idx & 7;
                cpa16(sA[nxt] + r * 144 + c * 16, Ag + (size_t)(m0 + r) * H_ + k0 + c * 8);
                cpa16(sB[nxt] + r * 144 + c * 16, Bg + (size_t)(n0 + r) * H_ + k0 + c * 8);
            }
            asm volatile("cp.async.commit_group;");
            asm volatile("cp.async.wait_group 1;");
        } else {
            asm volatile("cp.async.wait_group 0;");
        }
        __syncthreads();

        const uint32_t ab = sA[cur] + a_lane;
        const uint32_t bb2 = sB[cur] + b_lane;
        #pragma unroll
        for (int kd = 0; kd < 4; kd++) {
            unsigned af[4][4];
            #pragma unroll
            for (int mt = 0; mt < 4; mt++)
                ldsm4(af[mt], ab + mt * 16 * 144 + kd * 32);
            unsigned bfp[2][4];
            #pragma unroll
            for (int p = 0; p < 2; p++)
                ldsm4(bfp[p], bb2 + p * 16 * 144 + kd * 32);
            #pragma unroll
            for (int p = 0; p < 2; p++)
                #pragma unroll
                for (int mt = 0; mt < 4; mt++) {
                    mma16(acc[mt][2 * p],     af[mt], &bfp[p][0]);
                    mma16(acc[mt][2 * p + 1], af[mt], &bfp[p][2]);
                }
        }
        __syncthreads();
    }

    const int bb = m0 >> 11;
    const int s0 = m0 & (S_ - 1);

    if (z != 2) {
        __half* outp = (z == 0) ? g_q : g_k;
        #pragma unroll
        for (int mt = 0; mt < 4; mt++) {
            #pragma unroll
            for (int nt = 0; nt < 4; nt++) {
                const int c = n0 + wn * 32 + nt * 8 + 2 * j;
                const int h = c >> 6, d = c & 63;
                const float b0 = bias[c], b1 = bias[c + 1];
                #pragma unroll
                for (int hf = 0; hf < 2; hf++) {
                    const int m = m0 + wm * 64 + mt * 16 + g + hf * 8;
                    const int s = m & (S_ - 1);
                    __half2 o = __floats2half2_rn(
                        (acc[mt][nt][hf * 2 + 0] + b0) * oscale,
                        (acc[mt][nt][hf * 2 + 1] + b1) * oscale);
                    *reinterpret_cast<__half2*>(
                        outp + (((size_t)bb * NH_ + h) * S_ + s) * DH_ + d) = o;
                }
            }
        }
    } else {
        // V: stage transposed tile in smem, then coalesced 16B writes.
        __half* st = reinterpret_cast<__half*>(gsm);   // [128 n][136 m halves]
        #pragma unroll
        for (int mt = 0; mt < 4; mt++) {
            #pragma unroll
            for (int nt = 0; nt < 4; nt++) {
                const int cl = wn * 32 + nt * 8 + 2 * j;
                const float b0 = bias[n0 + cl], b1 = bias[n0 + cl + 1];
                #pragma unroll
                for (int hf = 0; hf < 2; hf++) {
                    const int ml = wm * 64 + mt * 16 + g + hf * 8;
                    st[cl * 136 + ml]       = __float2half_rn(acc[mt][nt][hf * 2 + 0] + b0);
                    st[(cl + 1) * 136 + ml] = __float2half_rn(acc[mt][nt][hf * 2 + 1] + b1);
                }
            }
        }
        __syncthreads();
        #pragma unroll
        for (int t = 0; t < 8; t++) {
            const int idx = t * 256 + tid;          // 2048 x 16B
            const int row = idx >> 4, c8 = idx & 15;
            uint4 v = *reinterpret_cast<uint4*>(&st[row * 136 + c8 * 8]);
            const int c = n0 + row;
            const int h = c >> 6, d = c & 63;
            *reinterpret_cast<uint4*>(
                g_v + (((size_t)bb * NH_ + h) * DH_ + d) * S_ + s0 + c8 * 8) = v;
        }
    }
}

// ---------------------------------------------------------------------------
// Kernel 2: fp16 flash attention. l folded into P@V via constant ones-column
// B-fragment; P = ex2.approx.f16x2 directly into A-fragments.
// ---------------------------------------------------------------------------
#define FQ_OFF 0
#define FK_OFF(b) (9216 + (b) * 4608)
#define FV_OFF(b) (18432 + (b) * 4608)
#define FM_OFF 27648
#define F_TOTAL_BYTES (55296 + 8192)

__global__ __launch_bounds__(256, 2) void flash_attn_h(
    const float* __restrict__ mask, float* __restrict__ out)
{
    extern __shared__ __half smh[];
    const uint32_t sb = (uint32_t)__cvta_generic_to_shared(smh);
    float* msks = reinterpret_cast<float*>(smh + FM_OFF);

    const int tid  = threadIdx.x;
    const int lane = tid & 31;
    const int wid  = tid >> 5;
    const int g = lane >> 2, j = lane & 3;

    const int qbase = blockIdx.x * 128;
    const int h = blockIdx.y, bb = blockIdx.z;
    const __half* Qg = g_q + ((size_t)bb * NH_ + h) * S_ * DH_;
    const __half* Kg = g_k + ((size_t)bb * NH_ + h) * S_ * DH_;
    const __half* Vt = g_v + ((size_t)bb * NH_ + h) * DH_ * S_;
    const float* mrow = mask + (size_t)bb * S_;

    #pragma unroll
    for (int t = 0; t < 2; t++) {
        const int i = t * 256 + tid;
        float4 mv = *reinterpret_cast<const float4*>(mrow + i * 4);
        mv.x *= LOG2E; mv.y *= LOG2E; mv.z *= LOG2E; mv.w *= LOG2E;
        *reinterpret_cast<float4*>(msks + i * 4) = mv;
    }

    #pragma unroll
    for (int t = 0; t < 4; t++) {
        const int f = t * 256 + tid;
        const int r = f >> 3, c = f & 7;
        cpa16(sb + FQ_OFF * 2 + r * 144 + c * 16, Qg + (size_t)(qbase + r) * DH_ + c * 8);
    }
    #pragma unroll
    for (int t = 0; t < 2; t++) {
        const int f = t * 256 + tid;
        const int r = f >> 3, c = f & 7;
        cpa16(sb + FK_OFF(0) * 2 + r * 144 + c * 16, Kg + (size_t)r * DH_ + c * 8);
        cpa16(sb + FV_OFF(0) * 2 + r * 144 + c * 16, Vt + (size_t)r * S_ + c * 8);
    }
    asm volatile("cp.async.commit_group;");

    const int lm = lane >> 3;
    const uint32_t qa = sb + FQ_OFF * 2
        + (uint32_t)((wid * 16 + (lane & 7) + (lm & 1) * 8) * 144 + (lane >> 4) * 16);
    const uint32_t kv_lane = (uint32_t)(((lm >> 1) * 8 + (lane & 7)) * 144 + (lm & 1) * 16);

    // Constant ones-column B fragment (n_local=0 => lanes with g==0 hold 1.0).
    unsigned bfl[2];
    bfl[0] = bfl[1] = (g == 0) ? 0x3C003C00u : 0u;

    float m0 = -1e30f, m1 = -1e30f;
    float O[8][4];
    float Ol[4] = {0.f, 0.f, 0.f, 0.f};   // l accumulator (ones column)
    #pragma unroll
    for (int nt = 0; nt < 8; nt++)
        #pragma unroll
        for (int r = 0; r < 4; r++) O[nt][r] = 0.f;

    const int prow = wid * 16 + g;

    const int NT = S_ / 64;
    for (int kc = 0; kc < NT; kc++) {
        const int cur = kc & 1;
        if (kc < NT - 1) {
            const int nxt = cur ^ 1;
            #pragma unroll
            for (int t = 0; t < 2; t++) {
                const int f = t * 256 + tid;
                const int r = f >> 3, c = f & 7;
                cpa16(sb + FK_OFF(nxt) * 2 + r * 144 + c * 16,
                      Kg + (size_t)((kc + 1) * 64 + r) * DH_ + c * 8);
                cpa16(sb + FV_OFF(nxt) * 2 + r * 144 + c * 16,
                      Vt + (size_t)r * S_ + (kc + 1) * 64 + c * 8);
            }
            asm volatile("cp.async.commit_group;");
            asm volatile("cp.async.wait_group 1;");
        } else {
            asm volatile("cp.async.wait_group 0;");
        }
        __syncthreads();

        const uint32_t kb = sb + FK_OFF(cur) * 2 + kv_lane;
        const uint32_t vb = sb + FV_OFF(cur) * 2 + kv_lane;

        // ---- S = Q @ K^T ----
        float Sa[8][4];
        #pragma unroll
        for (int nt = 0; nt < 8; nt++)
            #pragma unroll
            for (int r = 0; r < 4; r++) Sa[nt][r] = 0.f;

        #pragma unroll
        for (int kd = 0; kd < 4; kd++) {
            unsigned Qf[4];
            ldsm4(Qf, qa + kd * 32);
            #pragma unroll
            for (int p = 0; p < 4; p++) {
                unsigned bf[4];
                ldsm4(bf, kb + p * (16 * 144) + kd * 32);
                mma16(Sa[2 * p],     Qf, &bf[0]);
                mma16(Sa[2 * p + 1], Qf, &bf[2]);
            }
        }

        // ---- mask + tile max ----
        float tm0 = -1e30f, tm1 = -1e30f;
        #pragma unroll
        for (int nt = 0; nt < 8; nt++) {
            const float2 mk = *reinterpret_cast<const float2*>(
                &msks[kc * 64 + nt * 8 + 2 * j]);
            Sa[nt][0] += mk.x; Sa[nt][1] += mk.y;
            Sa[nt][2] += mk.x; Sa[nt][3] += mk.y;
            tm0 = fmaxf(tm0, fmaxf(Sa[nt][0], Sa[nt][1]));
            tm1 = fmaxf(tm1, fmaxf(Sa[nt][2], Sa[nt][3]));
        }
        tm0 = fmaxf(tm0, __shfl_xor_sync(0xffffffffu, tm0, 1));
        tm0 = fmaxf(tm0, __shfl_xor_sync(0xffffffffu, tm0, 2));
        tm1 = fmaxf(tm1, __shfl_xor_sync(0xffffffffu, tm1, 1));
        tm1 = fmaxf(tm1, __shfl_xor_sync(0xffffffffu, tm1, 2));

        const float nm0 = fmaxf(m0, tm0), nm1 = fmaxf(m1, tm1);
        const float al0 = ex2(m0 - nm0), al1 = ex2(m1 - nm1);
        m0 = nm0; m1 = nm1;

        // ---- P = 2^(S - m) via f16x2 MUFU, straight into A-fragments ----
        unsigned Pp[8][2];
        #pragma unroll
        for (int nt = 0; nt < 8; nt++) {
            Pp[nt][0] = h2exp2(packh2(Sa[nt][0] - nm0, Sa[nt][1] - nm0));
            Pp[nt][1] = h2exp2(packh2(Sa[nt][2] - nm1, Sa[nt][3] - nm1));
        }

        #pragma unroll
        for (int nt = 0; nt < 8; nt++) {
            O[nt][0] *= al0; O[nt][1] *= al0;
            O[nt][2] *= al1; O[nt][3] *= al1;
        }
        Ol[0] *= al0; Ol[1] *= al0; Ol[2] *= al1; Ol[3] *= al1;

        // ---- O += P @ V  (+ ones column accumulates l) ----
        #pragma unroll
        for (int kk = 0; kk < 4; kk++) {
            unsigned Pf[4];
            Pf[0] = Pp[2 * kk][0];
            Pf[1] = Pp[2 * kk][1];
            Pf[2] = Pp[2 * kk + 1][0];
            Pf[3] = Pp[2 * kk + 1][1];
            #pragma unroll
            for (int p = 0; p < 4; p++) {
                unsigned bf[4];
                ldsm4(bf, vb + p * (16 * 144) + kk * 32);
                mma16(O[2 * p],     Pf, &bf[0]);
                mma16(O[2 * p + 1], Pf, &bf[2]);
            }
            mma16(Ol, Pf, bfl);
        }
        __syncthreads();
    }

    // Epilogue: l lives in Ol[0]/Ol[2] of each quad's j==0 lane.
    const int qb = lane & 28;
    const float l0 = __shfl_sync(0xffffffffu, Ol[0], qb);
    const float l1 = __shfl_sync(0xffffffffu, Ol[2], qb);
    const float inv0 = 1.f / l0, inv1 = 1.f / l1;
    const int r0 = qbase + prow;
    #pragma unroll
    for (int nt = 0; nt < 8; nt++) {
        const int c = h * 64 + nt * 8 + 2 * j;
        float2 o0, o1;
        o0.x = O[nt][0] * inv0; o0.y = O[nt][1] * inv0;
        o1.x = O[nt][2] * inv1; o1.y = O[nt][3] * inv1;
        *reinterpret_cast<float2*>(out + ((size_t)bb * S_ + r0) * H_ + c) = o0;
        *reinterpret_cast<float2*>(out + ((size_t)bb * S_ + r0 + 8) * H_ + c) = o1;
    }
}

extern "C" void kernel_launch(void* const* d_in, const int* in_sizes, int n_in,
                              void* d_out, int out_size)
{
    const float* hs   = (const float*)d_in[0];
    const float* mask = (const float*)d_in[1];
    const float* Wq   = (const float*)d_in[2];
    const float* bq   = (const float*)d_in[3];
    const float* Wk   = (const float*)d_in[4];
    const float* bk   = (const float*)d_in[5];
    const float* Wv   = (const float*)d_in[6];
    const float* bv   = (const float*)d_in[7];
    float* out = (float*)d_out;

    cvt_hs<<<(B_ * S_ * H_) / (256 * 8), 256>>>(hs);
    dim3 gw(H_ / 32, H_ / 32, 3);
    wtrans<<<gw, 256>>>(Wq, Wk, Wv);

    const int smem_gemm = 18432 * 4;   // 72 KB (2 x A + 2 x B @ 144B rows)
    cudaFuncSetAttribute(qkv_gemm_h, cudaFuncAttributeMaxDynamicSharedMemorySize, smem_gemm);
    dim3 g1(H_ / 128, (B_ * S_) / 128, 3);
    qkv_gemm_h<<<g1, 256, smem_gemm>>>(bq, bk, bv);

    cudaFuncSetAttribute(flash_attn_h, cudaFuncAttributeMaxDynamicSharedMemorySize, F_TOTAL_BYTES);
    dim3 g2(S_ / 128, NH_, B_);
    flash_attn_h<<<g2, 256, F_TOTAL_BYTES>>>(mask, out);
}